// round 1
// baseline (speedup 1.0000x reference)
#include <cuda_runtime.h>

#define BB 16
#define CC 80
#define HH 128
#define WW 128
#define NN 50
#define CANDK 100

// Persistent scratch: gt heatmap as float bits. Zero-initialized at module load,
// and restored to all-zero every launch by the atomicExch in correct_kernel.
__device__ unsigned g_gt[BB * CC * HH * WW];   // ~84 MB
__device__ double g_cls_sum;
__device__ double g_off_sum;
__device__ double g_size_sum;
__device__ int    g_num_pos;

__global__ void init_kernel() {
    g_cls_sum = 0.0; g_off_sum = 0.0; g_size_sum = 0.0; g_num_pos = 0;
}

__device__ __forceinline__ float clampp(float x) {
    return fminf(fmaxf(x, 1e-4f), 0.9999f);
}

__device__ __forceinline__ float neg_base(float x) {
    float p = clampp(x);
    return p * p * __logf(1.0f - p);
}

// ---------------------------------------------------------------------------
// Focal base: sum over ALL elements of p^2 * log(1-p)  (gt assumed 0)
// ---------------------------------------------------------------------------
__global__ void focal_base_kernel(const float4* __restrict__ cls, int total4) {
    float acc = 0.f;
    int stride = gridDim.x * blockDim.x;
    for (int i = blockIdx.x * blockDim.x + threadIdx.x; i < total4; i += stride) {
        float4 v = cls[i];
        acc += neg_base(v.x) + neg_base(v.y) + neg_base(v.z) + neg_base(v.w);
    }
    #pragma unroll
    for (int o = 16; o; o >>= 1) acc += __shfl_down_sync(0xffffffffu, acc, o);
    __shared__ float ws[8];
    int lane = threadIdx.x & 31, w = threadIdx.x >> 5;
    if (lane == 0) ws[w] = acc;
    __syncthreads();
    if (threadIdx.x == 0) {
        double s = 0.0;
        int nw = blockDim.x >> 5;
        for (int i = 0; i < nw; i++) s += (double)ws[i];
        atomicAdd(&g_cls_sum, s);
    }
}

// ---------------------------------------------------------------------------
// Keypoint geometry shared by scatter and correct kernels
// ---------------------------------------------------------------------------
__device__ __forceinline__ void load_kp(const float* __restrict__ gt_box,
                                        const int* __restrict__ gt_class,
                                        int b, int n,
                                        bool& valid, int& ch, int& cx, int& cy) {
    int cls = gt_class[b * NN + n];
    valid = (cls != -1);
    ch = max(cls, 0);
    const float* bx = gt_box + (b * NN + n) * 4;
    float wv = bx[2] - bx[0];
    float hv = bx[3] - bx[1];
    cx = (int)floorf(floorf(wv / 2.0f) / 4.0f);
    cy = (int)floorf(floorf(hv / 2.0f) / 4.0f);
}

__constant__ int c_dx[8] = {-1,-1,-1, 0, 0, 1, 1, 1};
__constant__ int c_dy[8] = {-1, 0, 1,-1, 1,-1, 0, 1};

__global__ void scatter_kernel(const float* __restrict__ gt_box,
                               const int* __restrict__ gt_class) {
    int t = blockIdx.x * blockDim.x + threadIdx.x;
    if (t >= BB * NN) return;
    int b = t / NN, n = t % NN;
    bool valid; int ch, cx, cy;
    load_kp(gt_box, gt_class, b, n, valid, ch, cx, cy);
    if (!valid) return;
    const float ONE_V = 0.6065306597126334f;   // exp(-0.5)
    const float TWO_V = 0.36787944117144233f;  // exp(-1.0)
    if (cx >= 0 && cx < HH && cy >= 0 && cy < WW)
        atomicMax(&g_gt[((b * CC + ch) * HH + cx) * WW + cy], __float_as_uint(1.0f));
    bool interior = (cx >= 1) && (cy >= 1) && (cx + 1 < HH) && (cy + 1 < WW);
    if (interior) {
        #pragma unroll
        for (int k = 0; k < 8; k++) {
            int dx = c_dx[k], dy = c_dy[k];
            float v = (dx != 0 && dy != 0) ? TWO_V : ONE_V;
            atomicMax(&g_gt[((b * CC + ch) * HH + cx + dx) * WW + cy + dy],
                      __float_as_uint(v));
        }
    }
}

// Exchange-and-correct: each touched cell is processed exactly once (the
// thread whose atomicExch returns nonzero), and g_gt is left all-zero.
__global__ void correct_kernel(const float* __restrict__ cls,
                               const float* __restrict__ gt_box,
                               const int* __restrict__ gt_class) {
    int t = blockIdx.x * blockDim.x + threadIdx.x;
    if (t >= BB * NN) return;
    int b = t / NN, n = t % NN;
    bool valid; int ch, cx, cy;
    load_kp(gt_box, gt_class, b, n, valid, ch, cx, cy);
    if (!valid) return;
    double acc = 0.0;
    bool interior = (cx >= 1) && (cy >= 1) && (cx + 1 < HH) && (cy + 1 < WW);
    #pragma unroll
    for (int k = 0; k < 9; k++) {
        int x, y;
        if (k == 8) {
            if (cx < 0 || cx >= HH || cy < 0 || cy >= WW) continue;
            x = cx; y = cy;
        } else {
            if (!interior) continue;
            x = cx + c_dx[k]; y = cy + c_dy[k];
        }
        int cell = ((b * CC + ch) * HH + x) * WW + y;
        unsigned old = atomicExch(&g_gt[cell], 0u);
        if (old != 0u) {
            float g = __uint_as_float(old);
            float p = clampp(cls[cell]);
            float base = p * p * __logf(1.0f - p);
            float actual;
            if (g == 1.0f) {
                float q = 1.0f - p; float q2 = q * q;
                actual = q2 * q2 * __logf(p);
            } else {
                float q = 1.0f - g; float q2 = q * q;
                actual = q2 * q2 * base;
            }
            acc += (double)(actual - base);
        }
    }
    if (acc != 0.0) atomicAdd(&g_cls_sum, acc);
}

// ---------------------------------------------------------------------------
// Per-batch target: top-CANDK smallest cls values inside the window; directly
// accumulate L1 offset/size losses at the selected cells.
// ---------------------------------------------------------------------------
__global__ void target_kernel(const float* __restrict__ cls,
                              const float* __restrict__ offp,
                              const float* __restrict__ sizep,
                              const float* __restrict__ gt_box,
                              const int* __restrict__ gt_class) {
    __shared__ unsigned long long keys[4096];
    const int BD = 256;
    int b = blockIdx.x;
    int tid = threadIdx.x;

    int last = -1;
    for (int n = 0; n < NN; n++)
        if (gt_class[b * NN + n] != -1) last = n;
    if (last < 0) return;  // any_valid == false -> nothing selected

    const float* bx = gt_box + (b * NN + last) * 4;
    float wv = bx[2] - bx[0];
    float hv = bx[3] - bx[1];
    int ch = max(gt_class[b * NN + last], 0);
    int cx = (int)floorf(floorf(wv / 2.0f) / 4.0f);
    int cy = (int)floorf(floorf(hv / 2.0f) / 4.0f);
    int w4 = (int)floorf(wv / 4.0f);
    int h4 = (int)floorf(hv / 4.0f);
    // arithmetic >>1 == Python floor-div by 2
    int left   = max((cx - (w4 >> 1)) >> 1, 0);
    int right  = min((cx + (w4 >> 1)) >> 1, HH / 2);
    int top    = max((cy - (h4 >> 1)) >> 1, 0);
    int bottom = min((cy + (h4 >> 1)) >> 1, WW / 2);
    int wr = right - left, hc = bottom - top;
    int M = (wr > 0 && hc > 0) ? wr * hc : 0;

    int P = 1;
    while (P < M) P <<= 1;

    if (M > 0) {
        for (int t = tid; t < P; t += BD) {
            if (t < M) {
                int r = left + t / hc;
                int c = top + t % hc;
                float v = cls[((b * CC + ch) * HH + r) * WW + c];
                keys[t] = (((unsigned long long)__float_as_uint(v)) << 32)
                        | (unsigned)(r * WW + c);
            } else {
                keys[t] = ~0ull;
            }
        }
        __syncthreads();
        // bitonic sort ascending: (val asc, idx asc) == jax top_k(-vals) order
        for (int k = 2; k <= P; k <<= 1) {
            for (int j = k >> 1; j > 0; j >>= 1) {
                for (int i = tid; i < P; i += BD) {
                    int ixj = i ^ j;
                    if (ixj > i) {
                        unsigned long long a = keys[i], c2 = keys[ixj];
                        bool up = ((i & k) == 0);
                        if ((a > c2) == up) { keys[i] = c2; keys[ixj] = a; }
                    }
                }
                __syncthreads();
            }
        }
    }

    int K = min(CANDK, M);
    float cxf = wv / 2.0f / 4.0f;
    float cyf = hv / 2.0f / 4.0f;
    float off0 = cxf - floorf(cxf);
    float off1 = cyf - floorf(cyf);

    float accO = 0.f, accS = 0.f;
    for (int t = tid; t < K; t += BD) {
        unsigned idx = (unsigned)(keys[t] & 0xffffffffu);
        int i = idx / WW, j = idx % WW;
        float o0 = offp[((b * 2 + 0) * HH + i) * WW + j];
        float o1 = offp[((b * 2 + 1) * HH + i) * WW + j];
        float s0 = sizep[((b * 2 + 0) * HH + i) * WW + j];
        float s1 = sizep[((b * 2 + 1) * HH + i) * WW + j];
        accO += fabsf(o0 - off0) + fabsf(o1 - off1);
        accS += fabsf(s0 - wv) + fabsf(s1 - hv);
    }
    #pragma unroll
    for (int o = 16; o; o >>= 1) {
        accO += __shfl_down_sync(0xffffffffu, accO, o);
        accS += __shfl_down_sync(0xffffffffu, accS, o);
    }
    __shared__ float wsO[8], wsS[8];
    if ((tid & 31) == 0) { wsO[tid >> 5] = accO; wsS[tid >> 5] = accS; }
    __syncthreads();
    if (tid == 0) {
        float sO = 0.f, sS = 0.f;
        for (int i = 0; i < BD / 32; i++) { sO += wsO[i]; sS += wsS[i]; }
        atomicAdd(&g_off_sum, (double)sO);
        atomicAdd(&g_size_sum, (double)sS);
        atomicAdd(&g_num_pos, K);
    }
}

__global__ void finalize_kernel(float* __restrict__ out) {
    double np = (double)max(g_num_pos, 1);
    double cls_loss = -g_cls_sum / (double)(BB * HH * WW);
    out[0] = (float)(cls_loss + 0.1 * (g_size_sum / np) + (g_off_sum / np));
}

extern "C" void kernel_launch(void* const* d_in, const int* in_sizes, int n_in,
                              void* d_out, int out_size) {
    const float* cls_pred    = (const float*)d_in[0];
    const float* offset_pred = (const float*)d_in[1];
    const float* size_pred   = (const float*)d_in[2];
    const float* gt_box      = (const float*)d_in[3];
    const int*   gt_class    = (const int*)d_in[4];
    float* out = (float*)d_out;

    (void)in_sizes; (void)n_in; (void)out_size;

    init_kernel<<<1, 1>>>();

    int total4 = (BB * CC * HH * WW) / 4;
    focal_base_kernel<<<2048, 256>>>((const float4*)cls_pred, total4);

    int kp_threads = BB * NN;
    scatter_kernel<<<(kp_threads + 127) / 128, 128>>>(gt_box, gt_class);
    correct_kernel<<<(kp_threads + 127) / 128, 128>>>(cls_pred, gt_box, gt_class);

    target_kernel<<<BB, 256>>>(cls_pred, offset_pred, size_pred, gt_box, gt_class);

    finalize_kernel<<<1, 1>>>(out);
}

// round 2
// speedup vs baseline: 1.3150x; 1.3150x over previous
#include <cuda_runtime.h>

#define BB 16
#define CC 80
#define HH 128
#define WW 128
#define NN 50
#define CANDK 100
#define FBLK 1024
#define HSZ 1024
#define HEMPTY 0xFFFFFFFFu

// Per-slot deterministic partials (no init kernel needed: every slot is
// written unconditionally each launch).
__device__ double g_focal[FBLK];
__device__ float  g_corr[BB];
__device__ float  g_off[BB];
__device__ float  g_size[BB];
__device__ int    g_npos[BB];

__device__ __forceinline__ float clampp(float x) {
    return fminf(fmaxf(x, 1e-4f), 0.9999f);
}
__device__ __forceinline__ float neg_base(float x) {
    float p = clampp(x);
    return p * p * __logf(1.0f - p);
}

// 256-thread block reduce; result valid on tid 0.
__device__ __forceinline__ float block_reduce256(float v, float* ws) {
    int lane = threadIdx.x & 31, w = threadIdx.x >> 5;
    #pragma unroll
    for (int o = 16; o; o >>= 1) v += __shfl_down_sync(0xffffffffu, v, o);
    if (lane == 0) ws[w] = v;
    __syncthreads();
    float s = 0.f;
    if (threadIdx.x == 0) {
        #pragma unroll
        for (int i = 0; i < 8; i++) s += ws[i];
    }
    __syncthreads();
    return s;
}

// ---------------------------------------------------------------------------
// Focal base: sum over ALL elements of p^2*log(1-p) (gt assumed 0 everywhere)
// ---------------------------------------------------------------------------
__global__ void focal_base_kernel(const float4* __restrict__ cls, int total4) {
    float a0 = 0.f, a1 = 0.f, a2 = 0.f, a3 = 0.f;
    int stride = gridDim.x * blockDim.x;
    int i = blockIdx.x * blockDim.x + threadIdx.x;
    // 4-way independent accumulators for memory-level parallelism
    for (; i + 3 * stride < total4; i += 4 * stride) {
        float4 v0 = cls[i];
        float4 v1 = cls[i + stride];
        float4 v2 = cls[i + 2 * stride];
        float4 v3 = cls[i + 3 * stride];
        a0 += neg_base(v0.x) + neg_base(v0.y) + neg_base(v0.z) + neg_base(v0.w);
        a1 += neg_base(v1.x) + neg_base(v1.y) + neg_base(v1.z) + neg_base(v1.w);
        a2 += neg_base(v2.x) + neg_base(v2.y) + neg_base(v2.z) + neg_base(v2.w);
        a3 += neg_base(v3.x) + neg_base(v3.y) + neg_base(v3.z) + neg_base(v3.w);
    }
    for (; i < total4; i += stride) {
        float4 v = cls[i];
        a0 += neg_base(v.x) + neg_base(v.y) + neg_base(v.z) + neg_base(v.w);
    }
    __shared__ float ws[8];
    float s = block_reduce256((a0 + a1) + (a2 + a3), ws);
    if (threadIdx.x == 0) g_focal[blockIdx.x] = (double)s;
}

// ---------------------------------------------------------------------------
// Fused per-batch kernel: gt hash-dedup + focal correction + top-K target
// ---------------------------------------------------------------------------
__global__ void __launch_bounds__(256, 1)
batch_kernel(const float* __restrict__ cls,
             const float* __restrict__ offp,
             const float* __restrict__ sizep,
             const float* __restrict__ gt_box,
             const int* __restrict__ gt_class) {
    __shared__ unsigned hkey[HSZ];
    __shared__ unsigned hval[HSZ];
    __shared__ unsigned long long keys[HH / 2 * WW / 2];  // 4096 * 8B
    __shared__ int hist[256];
    __shared__ float ws[8];
    __shared__ int s_last;
    __shared__ unsigned long long s_prefix;
    __shared__ int s_kth;

    const int b = blockIdx.x;
    const int tid = threadIdx.x;
    const float* clsb = cls + (size_t)b * CC * HH * WW;

    // init hash + find last valid keypoint
    for (int s = tid; s < HSZ; s += 256) { hkey[s] = HEMPTY; hval[s] = 0u; }
    if (tid == 0) s_last = -1;
    __syncthreads();
    if (tid < NN && gt_class[b * NN + tid] != -1) atomicMax(&s_last, tid);
    __syncthreads();

    // --- scatter gt into shared hash (max-dedup) ---
    if (tid < NN) {
        int clsv = gt_class[b * NN + tid];
        if (clsv != -1) {
            int ch = max(clsv, 0);
            const float* bx = gt_box + (b * NN + tid) * 4;
            float wv = bx[2] - bx[0];
            float hv = bx[3] - bx[1];
            int cx = (int)floorf(floorf(wv * 0.5f) * 0.25f);
            int cy = (int)floorf(floorf(hv * 0.5f) * 0.25f);
            const float ONE_V = 0.6065306597126334f;   // exp(-0.5)
            const float TWO_V = 0.36787944117144233f;  // exp(-1.0)
            bool interior = (cx >= 1) && (cy >= 1) && (cx + 1 < HH) && (cy + 1 < WW);
            #pragma unroll
            for (int k = 0; k < 9; k++) {
                int dx = k / 3 - 1, dy = k % 3 - 1;
                float v;
                if (dx == 0 && dy == 0) {
                    if (cx < 0 || cx >= HH || cy < 0 || cy >= WW) continue;
                    v = 1.0f;
                } else {
                    if (!interior) continue;
                    v = (dx != 0 && dy != 0) ? TWO_V : ONE_V;
                }
                unsigned cell = (unsigned)(((ch * HH + cx + dx) * WW) + cy + dy);
                unsigned slot = (cell * 2654435761u) & (HSZ - 1);
                while (true) {
                    unsigned prev = atomicCAS(&hkey[slot], HEMPTY, cell);
                    if (prev == HEMPTY || prev == cell) {
                        atomicMax(&hval[slot], __float_as_uint(v));
                        break;
                    }
                    slot = (slot + 1) & (HSZ - 1);
                }
            }
        }
    }
    __syncthreads();

    // --- focal corrections at the dedup'd cells ---
    float corr = 0.f;
    for (int s = tid; s < HSZ; s += 256) {
        unsigned cell = hkey[s];
        if (cell != HEMPTY) {
            float g = __uint_as_float(hval[s]);
            float p = clampp(clsb[cell]);
            float base = p * p * __logf(1.0f - p);
            float actual;
            if (g == 1.0f) {
                float q = 1.0f - p, q2 = q * q;
                actual = q2 * q2 * __logf(p);
            } else {
                float q = 1.0f - g, q2 = q * q;
                actual = q2 * q2 * base;
            }
            corr += actual - base;
        }
    }
    float corr_tot = block_reduce256(corr, ws);
    if (tid == 0) g_corr[b] = corr_tot;

    // --- target: top-CANDK smallest cls in window of the LAST valid kp ---
    int last = s_last;
    if (last < 0) {
        if (tid == 0) { g_off[b] = 0.f; g_size[b] = 0.f; g_npos[b] = 0; }
        return;
    }
    const float* bx = gt_box + (b * NN + last) * 4;
    float wv = bx[2] - bx[0];
    float hv = bx[3] - bx[1];
    int ch = max(gt_class[b * NN + last], 0);
    int cx = (int)floorf(floorf(wv * 0.5f) * 0.25f);
    int cy = (int)floorf(floorf(hv * 0.5f) * 0.25f);
    int w4 = (int)floorf(wv * 0.25f);
    int h4 = (int)floorf(hv * 0.25f);
    int left   = max((cx - (w4 >> 1)) >> 1, 0);   // >>1 == floor-div 2
    int right  = min((cx + (w4 >> 1)) >> 1, HH / 2);
    int top    = max((cy - (h4 >> 1)) >> 1, 0);
    int bottom = min((cy + (h4 >> 1)) >> 1, WW / 2);
    int wr = right - left, hc = bottom - top;
    int M = (wr > 0 && hc > 0) ? wr * hc : 0;
    int K = min(CANDK, M);

    if (M == 0) {
        if (tid == 0) { g_off[b] = 0.f; g_size[b] = 0.f; g_npos[b] = 0; }
        return;
    }

    // load window as packed (valbits<<32 | flat_idx): asc sort == jax order
    for (int t = tid; t < M; t += 256) {
        int r = left + t / hc;
        int c = top + t % hc;
        float v = clsb[(ch * HH + r) * WW + c];
        keys[t] = (((unsigned long long)__float_as_uint(v)) << 32)
                | (unsigned)(r * WW + c);
    }
    __syncthreads();

    unsigned long long T = ~0ull;  // M <= K: select all
    if (M > K) {
        // radix-select the K-th smallest key, 8 bits at a time (MSB first)
        if (tid == 0) { s_prefix = 0ull; s_kth = K; }
        __syncthreads();
        for (int d = 56; d >= 0; d -= 8) {
            hist[tid] = 0;  // blockDim == 256
            __syncthreads();
            unsigned long long pfx = s_prefix;
            for (int i = tid; i < M; i += 256) {
                unsigned long long key = keys[i];
                bool act = (d == 56) || ((key >> (d + 8)) == pfx);
                if (act) atomicAdd(&hist[(int)((key >> d) & 255)], 1);
            }
            __syncthreads();
            if (tid == 0) {
                int cum = 0, bin = 0;
                for (; bin < 256; bin++) {
                    if (cum + hist[bin] >= s_kth) break;
                    cum += hist[bin];
                }
                s_kth -= cum;
                s_prefix = (pfx << 8) | (unsigned)bin;
            }
            __syncthreads();
        }
        T = s_prefix;
    }

    float cxf = wv * 0.5f * 0.25f;
    float cyf = hv * 0.5f * 0.25f;
    float off0 = cxf - floorf(cxf);
    float off1 = cyf - floorf(cyf);

    float accO = 0.f, accS = 0.f;
    for (int t = tid; t < M; t += 256) {
        if (keys[t] <= T) {
            unsigned idx = (unsigned)(keys[t] & 0xffffffffu);
            int i = idx / WW, j = idx % WW;
            float o0 = offp[((b * 2 + 0) * HH + i) * WW + j];
            float o1 = offp[((b * 2 + 1) * HH + i) * WW + j];
            float s0 = sizep[((b * 2 + 0) * HH + i) * WW + j];
            float s1 = sizep[((b * 2 + 1) * HH + i) * WW + j];
            accO += fabsf(o0 - off0) + fabsf(o1 - off1);
            accS += fabsf(s0 - wv) + fabsf(s1 - hv);
        }
    }
    float sO = block_reduce256(accO, ws);
    float sS = block_reduce256(accS, ws);
    if (tid == 0) {
        g_off[b] = sO;
        g_size[b] = sS;
        g_npos[b] = K;
    }
}

// ---------------------------------------------------------------------------
// Finalize: deterministic sum of all partials
// ---------------------------------------------------------------------------
__global__ void finalize_kernel(float* __restrict__ out) {
    __shared__ double wsd[8];
    int tid = threadIdx.x;
    double acc = 0.0;
    for (int i = tid; i < FBLK; i += 256) acc += g_focal[i];
    int lane = tid & 31, w = tid >> 5;
    #pragma unroll
    for (int o = 16; o; o >>= 1) acc += __shfl_down_sync(0xffffffffu, acc, o);
    if (lane == 0) wsd[w] = acc;
    __syncthreads();
    if (tid == 0) {
        double fsum = 0.0;
        #pragma unroll
        for (int i = 0; i < 8; i++) fsum += wsd[i];
        double corr = 0.0, offs = 0.0, szs = 0.0;
        int npos = 0;
        for (int b = 0; b < BB; b++) {
            corr += (double)g_corr[b];
            offs += (double)g_off[b];
            szs  += (double)g_size[b];
            npos += g_npos[b];
        }
        double np = (double)max(npos, 1);
        double cls_loss = -(fsum + corr) / (double)(BB * HH * WW);
        out[0] = (float)(cls_loss + 0.1 * (szs / np) + (offs / np));
    }
}

extern "C" void kernel_launch(void* const* d_in, const int* in_sizes, int n_in,
                              void* d_out, int out_size) {
    const float* cls_pred    = (const float*)d_in[0];
    const float* offset_pred = (const float*)d_in[1];
    const float* size_pred   = (const float*)d_in[2];
    const float* gt_box      = (const float*)d_in[3];
    const int*   gt_class    = (const int*)d_in[4];
    float* out = (float*)d_out;
    (void)in_sizes; (void)n_in; (void)out_size;

    int total4 = (BB * CC * HH * WW) / 4;
    focal_base_kernel<<<FBLK, 256>>>((const float4*)cls_pred, total4);
    batch_kernel<<<BB, 256>>>(cls_pred, offset_pred, size_pred, gt_box, gt_class);
    finalize_kernel<<<1, 256>>>(out);
}

// round 3
// speedup vs baseline: 1.5038x; 1.1435x over previous
#include <cuda_runtime.h>

#define BB 16
#define CC 80
#define HH 128
#define WW 128
#define NN 50
#define CANDK 100
#define FBLK 1024
#define HSZ 1024
#define HEMPTY 0xFFFFFFFFu
#define LN2 0.6931471805599453f

// Per-slot deterministic partials (every slot written unconditionally each launch).
__device__ double g_focal[FBLK];
__device__ float  g_corr[BB];
__device__ float  g_off[BB];
__device__ float  g_size[BB];
__device__ int    g_npos[BB];

__device__ __forceinline__ float clampp(float x) {
    return fminf(fmaxf(x, 1e-4f), 0.9999f);
}
// p^2 * lg2(1-p): one MUFU + mul + fma; ln2 factored out of the whole sum
__device__ __forceinline__ float nb2(float x) {
    float p = clampp(x);
    return p * p * __log2f(1.0f - p);
}

// 256-thread block reduce; result valid on tid 0.
__device__ __forceinline__ float block_reduce256(float v, float* ws) {
    int lane = threadIdx.x & 31, w = threadIdx.x >> 5;
    #pragma unroll
    for (int o = 16; o; o >>= 1) v += __shfl_down_sync(0xffffffffu, v, o);
    if (lane == 0) ws[w] = v;
    __syncthreads();
    float s = 0.f;
    if (threadIdx.x == 0) {
        #pragma unroll
        for (int i = 0; i < 8; i++) s += ws[i];
    }
    __syncthreads();
    return s;
}

// ---------------------------------------------------------------------------
// Focal base: sum over ALL elements of p^2*log(1-p)  (gt assumed 0 everywhere)
// ---------------------------------------------------------------------------
__global__ void focal_base_kernel(const float4* __restrict__ cls, int total4) {
    float a0 = 0.f, a1 = 0.f, a2 = 0.f, a3 = 0.f;
    int stride = gridDim.x * blockDim.x;
    int i = blockIdx.x * blockDim.x + threadIdx.x;
    for (; i + 3 * stride < total4; i += 4 * stride) {
        float4 v0 = cls[i];
        float4 v1 = cls[i + stride];
        float4 v2 = cls[i + 2 * stride];
        float4 v3 = cls[i + 3 * stride];
        a0 += nb2(v0.x) + nb2(v0.y) + nb2(v0.z) + nb2(v0.w);
        a1 += nb2(v1.x) + nb2(v1.y) + nb2(v1.z) + nb2(v1.w);
        a2 += nb2(v2.x) + nb2(v2.y) + nb2(v2.z) + nb2(v2.w);
        a3 += nb2(v3.x) + nb2(v3.y) + nb2(v3.z) + nb2(v3.w);
    }
    for (; i < total4; i += stride) {
        float4 v = cls[i];
        a0 += nb2(v.x) + nb2(v.y) + nb2(v.z) + nb2(v.w);
    }
    __shared__ float ws[8];
    float s = block_reduce256((a0 + a1) + (a2 + a3), ws);
    if (threadIdx.x == 0) g_focal[blockIdx.x] = (double)s * (double)LN2;
}

// ---------------------------------------------------------------------------
// Fused per-batch kernel: gt hash-dedup + focal correction + top-K target
// ---------------------------------------------------------------------------
__global__ void __launch_bounds__(256, 1)
batch_kernel(const float* __restrict__ cls,
             const float* __restrict__ offp,
             const float* __restrict__ sizep,
             const float* __restrict__ gt_box,
             const int* __restrict__ gt_class) {
    __shared__ unsigned hkey[HSZ];
    __shared__ unsigned hval[HSZ];
    __shared__ unsigned long long keys[HH / 2 * WW / 2];  // 4096 * 8B
    __shared__ int hist[256];
    __shared__ int wsum[8];
    __shared__ float ws[8];
    __shared__ int s_last;
    __shared__ unsigned long long s_prefix;
    __shared__ int s_kth;

    const int b = blockIdx.x;
    const int tid = threadIdx.x;
    const int lane = tid & 31, wrp = tid >> 5;
    const float* clsb = cls + (size_t)b * CC * HH * WW;

    for (int s = tid; s < HSZ; s += 256) { hkey[s] = HEMPTY; hval[s] = 0u; }
    if (tid == 0) s_last = -1;
    __syncthreads();
    if (tid < NN && gt_class[b * NN + tid] != -1) atomicMax(&s_last, tid);
    __syncthreads();

    // --- scatter gt into shared hash (max-dedup) ---
    if (tid < NN) {
        int clsv = gt_class[b * NN + tid];
        if (clsv != -1) {
            int ch = max(clsv, 0);
            const float* bx = gt_box + (b * NN + tid) * 4;
            float wv = bx[2] - bx[0];
            float hv = bx[3] - bx[1];
            int cx = (int)floorf(floorf(wv * 0.5f) * 0.25f);
            int cy = (int)floorf(floorf(hv * 0.5f) * 0.25f);
            const float ONE_V = 0.6065306597126334f;   // exp(-0.5)
            const float TWO_V = 0.36787944117144233f;  // exp(-1.0)
            bool interior = (cx >= 1) && (cy >= 1) && (cx + 1 < HH) && (cy + 1 < WW);
            #pragma unroll
            for (int k = 0; k < 9; k++) {
                int dx = k / 3 - 1, dy = k % 3 - 1;
                float v;
                if (dx == 0 && dy == 0) {
                    if (cx < 0 || cx >= HH || cy < 0 || cy >= WW) continue;
                    v = 1.0f;
                } else {
                    if (!interior) continue;
                    v = (dx != 0 && dy != 0) ? TWO_V : ONE_V;
                }
                unsigned cell = (unsigned)(((ch * HH + cx + dx) * WW) + cy + dy);
                unsigned slot = (cell * 2654435761u) & (HSZ - 1);
                while (true) {
                    unsigned prev = atomicCAS(&hkey[slot], HEMPTY, cell);
                    if (prev == HEMPTY || prev == cell) {
                        atomicMax(&hval[slot], __float_as_uint(v));
                        break;
                    }
                    slot = (slot + 1) & (HSZ - 1);
                }
            }
        }
    }
    __syncthreads();

    // --- focal corrections at the dedup'd cells ---
    float corr = 0.f;
    for (int s = tid; s < HSZ; s += 256) {
        unsigned cell = hkey[s];
        if (cell != HEMPTY) {
            float g = __uint_as_float(hval[s]);
            float p = clampp(clsb[cell]);
            float base = p * p * __logf(1.0f - p);
            float actual;
            if (g == 1.0f) {
                float q = 1.0f - p, q2 = q * q;
                actual = q2 * q2 * __logf(p);
            } else {
                float q = 1.0f - g, q2 = q * q;
                actual = q2 * q2 * base;
            }
            corr += actual - base;
        }
    }
    float corr_tot = block_reduce256(corr, ws);
    if (tid == 0) g_corr[b] = corr_tot;

    // --- target: top-CANDK smallest cls in window of the LAST valid kp ---
    int last = s_last;
    if (last < 0) {
        if (tid == 0) { g_off[b] = 0.f; g_size[b] = 0.f; g_npos[b] = 0; }
        return;
    }
    const float* bx = gt_box + (b * NN + last) * 4;
    float wv = bx[2] - bx[0];
    float hv = bx[3] - bx[1];
    int ch = max(gt_class[b * NN + last], 0);
    int cx = (int)floorf(floorf(wv * 0.5f) * 0.25f);
    int cy = (int)floorf(floorf(hv * 0.5f) * 0.25f);
    int w4 = (int)floorf(wv * 0.25f);
    int h4 = (int)floorf(hv * 0.25f);
    int left   = max((cx - (w4 >> 1)) >> 1, 0);   // >>1 == floor-div 2
    int right  = min((cx + (w4 >> 1)) >> 1, HH / 2);
    int top    = max((cy - (h4 >> 1)) >> 1, 0);
    int bottom = min((cy + (h4 >> 1)) >> 1, WW / 2);
    int wr = right - left, hc = bottom - top;
    int M = (wr > 0 && hc > 0) ? wr * hc : 0;
    int K = min(CANDK, M);

    if (M == 0) {
        if (tid == 0) { g_off[b] = 0.f; g_size[b] = 0.f; g_npos[b] = 0; }
        return;
    }

    // packed (valbits<<32 | flat_idx): ascending order == jax top_k(-vals) order
    for (int t = tid; t < M; t += 256) {
        int r = left + t / hc;
        int c = top + t % hc;
        float v = clsb[(ch * HH + r) * WW + c];
        keys[t] = (((unsigned long long)__float_as_uint(v)) << 32)
                | (unsigned)(r * WW + c);
    }
    __syncthreads();

    unsigned long long T = ~0ull;  // M <= K: select all
    if (M > K) {
        // radix-select K-th smallest key. idx < 16384 -> bits [16,32) are
        // always zero: skip those two digits (prefix <<= 16 after pass 3).
        if (tid == 0) { s_prefix = 0ull; s_kth = K; }
        __syncthreads();
        const int digits[6] = {56, 48, 40, 32, 8, 0};
        #pragma unroll
        for (int pi = 0; pi < 6; pi++) {
            int d = digits[pi];
            hist[tid] = 0;
            __syncthreads();
            unsigned long long pfx = s_prefix;
            int kth = s_kth;
            for (int i = tid; i < M; i += 256) {
                unsigned long long key = keys[i];
                bool act = (d == 56) || ((key >> (d + 8)) == pfx);
                if (act) atomicAdd(&hist[(int)((key >> d) & 255)], 1);
            }
            __syncthreads();
            // parallel inclusive scan over 256 bins (thread tid owns bin tid)
            int h0 = hist[tid];
            int h = h0;
            #pragma unroll
            for (int o = 1; o < 32; o <<= 1) {
                int n = __shfl_up_sync(0xffffffffu, h, o);
                if (lane >= o) h += n;
            }
            if (lane == 31) wsum[wrp] = h;
            __syncthreads();
            if (tid < 8) {
                int s = wsum[tid];
                #pragma unroll
                for (int o = 1; o < 8; o <<= 1) {
                    int n = __shfl_up_sync(0xffu, s, o);
                    if (tid >= o) s += n;
                }
                wsum[tid] = s;
            }
            __syncthreads();
            int cum = h + (wrp ? wsum[wrp - 1] : 0);
            int prev = cum - h0;
            if (prev < kth && kth <= cum) {     // exactly one thread
                s_kth = kth - prev;
                unsigned long long np = (pfx << 8) | (unsigned)tid;
                if (pi == 3) np <<= 16;         // skip always-zero bits [16,32)
                s_prefix = np;
            }
            __syncthreads();
        }
        T = s_prefix;
    }

    float cxf = wv * 0.5f * 0.25f;
    float cyf = hv * 0.5f * 0.25f;
    float off0 = cxf - floorf(cxf);
    float off1 = cyf - floorf(cyf);

    float accO = 0.f, accS = 0.f;
    for (int t = tid; t < M; t += 256) {
        if (keys[t] <= T) {
            unsigned idx = (unsigned)(keys[t] & 0xffffffffu);
            int i = idx / WW, j = idx % WW;
            float o0 = offp[((b * 2 + 0) * HH + i) * WW + j];
            float o1 = offp[((b * 2 + 1) * HH + i) * WW + j];
            float s0 = sizep[((b * 2 + 0) * HH + i) * WW + j];
            float s1 = sizep[((b * 2 + 1) * HH + i) * WW + j];
            accO += fabsf(o0 - off0) + fabsf(o1 - off1);
            accS += fabsf(s0 - wv) + fabsf(s1 - hv);
        }
    }
    float sO = block_reduce256(accO, ws);
    float sS = block_reduce256(accS, ws);
    if (tid == 0) {
        g_off[b] = sO;
        g_size[b] = sS;
        g_npos[b] = K;
    }
}

// ---------------------------------------------------------------------------
// Finalize: deterministic sum of all partials
// ---------------------------------------------------------------------------
__global__ void finalize_kernel(float* __restrict__ out) {
    __shared__ double wsd[8];
    int tid = threadIdx.x;
    double acc = 0.0;
    for (int i = tid; i < FBLK; i += 256) acc += g_focal[i];
    int lane = tid & 31, w = tid >> 5;
    #pragma unroll
    for (int o = 16; o; o >>= 1) acc += __shfl_down_sync(0xffffffffu, acc, o);
    if (lane == 0) wsd[w] = acc;
    __syncthreads();
    if (tid == 0) {
        double fsum = 0.0;
        #pragma unroll
        for (int i = 0; i < 8; i++) fsum += wsd[i];
        double corr = 0.0, offs = 0.0, szs = 0.0;
        int npos = 0;
        for (int b = 0; b < BB; b++) {
            corr += (double)g_corr[b];
            offs += (double)g_off[b];
            szs  += (double)g_size[b];
            npos += g_npos[b];
        }
        double np = (double)max(npos, 1);
        double cls_loss = -(fsum + corr) / (double)(BB * HH * WW);
        out[0] = (float)(cls_loss + 0.1 * (szs / np) + (offs / np));
    }
}

extern "C" void kernel_launch(void* const* d_in, const int* in_sizes, int n_in,
                              void* d_out, int out_size) {
    const float* cls_pred    = (const float*)d_in[0];
    const float* offset_pred = (const float*)d_in[1];
    const float* size_pred   = (const float*)d_in[2];
    const float* gt_box      = (const float*)d_in[3];
    const int*   gt_class    = (const int*)d_in[4];
    float* out = (float*)d_out;
    (void)in_sizes; (void)n_in; (void)out_size;

    // Fork a side stream inside capture so batch_kernel overlaps focal_base.
    // (Stream/event creation is a host-side op, legal during capture; they are
    // intentionally not destroyed here — destroying a stream mid-capture is
    // illegal, and kernel_launch is only invoked a handful of times.)
    cudaStream_t s2;
    cudaStreamCreateWithFlags(&s2, cudaStreamNonBlocking);
    cudaEvent_t e1, e2;
    cudaEventCreateWithFlags(&e1, cudaEventDisableTiming);
    cudaEventCreateWithFlags(&e2, cudaEventDisableTiming);

    cudaEventRecord(e1, 0);
    cudaStreamWaitEvent(s2, e1, 0);

    int total4 = (BB * CC * HH * WW) / 4;
    focal_base_kernel<<<FBLK, 256, 0, 0>>>((const float4*)cls_pred, total4);
    batch_kernel<<<BB, 256, 0, s2>>>(cls_pred, offset_pred, size_pred,
                                     gt_box, gt_class);

    cudaEventRecord(e2, s2);
    cudaStreamWaitEvent(0, e2, 0);
    finalize_kernel<<<1, 256, 0, 0>>>(out);
}

// round 4
// speedup vs baseline: 1.6094x; 1.0702x over previous
#include <cuda_runtime.h>

#define BB 16
#define CC 80
#define HH 128
#define WW 128
#define NN 50
#define CANDK 100
#define FBLK 1024
#define NBLK (FBLK + BB)
#define HSZ 1024
#define HEMPTY 0xFFFFFFFFu
#define LN2 0.6931471805599453

// Partials (every slot written unconditionally each launch) + done counter
// (zero at load; reset to zero by the last block each launch -> replay-safe).
__device__ double g_focal[FBLK];
__device__ float  g_corr[BB];
__device__ float  g_off[BB];
__device__ float  g_size[BB];
__device__ int    g_npos[BB];
__device__ int    g_done;

__device__ __forceinline__ float clampp(float x) {
    return fminf(fmaxf(x, 1e-4f), 0.9999f);
}
// p^2 * lg2(1-p): ln2 factored out once per block
__device__ __forceinline__ float nb2(float x) {
    float p = clampp(x);
    return p * p * __log2f(1.0f - p);
}

__global__ void fused_kernel(const float4* __restrict__ cls4,
                             const float* __restrict__ cls,
                             const float* __restrict__ offp,
                             const float* __restrict__ sizep,
                             const float* __restrict__ gt_box,
                             const int* __restrict__ gt_class,
                             float* __restrict__ out) {
    __shared__ unsigned hkey[HSZ];
    __shared__ unsigned hval[HSZ];
    __shared__ int hist[256];
    __shared__ int wsum[8];
    __shared__ float wsf[8];
    __shared__ double wsd[8];
    __shared__ int s_last;
    __shared__ unsigned long long s_prefix;
    __shared__ int s_kth;
    __shared__ int s_flag;

    const int tid = threadIdx.x;
    const int lane = tid & 31, wrp = tid >> 5;

    if (blockIdx.x >= BB) {
        // ================= focal partial (blocks BB..NBLK-1) =================
        const int total4 = BB * CC * HH * WW / 4;
        const int stride = FBLK * 256;
        int i = (blockIdx.x - BB) * 256 + tid;
        float a0 = 0.f, a1 = 0.f, a2 = 0.f, a3 = 0.f;
        for (; i + 3 * stride < total4; i += 4 * stride) {
            float4 v0 = __ldcs(cls4 + i);
            float4 v1 = __ldcs(cls4 + i + stride);
            float4 v2 = __ldcs(cls4 + i + 2 * stride);
            float4 v3 = __ldcs(cls4 + i + 3 * stride);
            a0 += nb2(v0.x) + nb2(v0.y) + nb2(v0.z) + nb2(v0.w);
            a1 += nb2(v1.x) + nb2(v1.y) + nb2(v1.z) + nb2(v1.w);
            a2 += nb2(v2.x) + nb2(v2.y) + nb2(v2.z) + nb2(v2.w);
            a3 += nb2(v3.x) + nb2(v3.y) + nb2(v3.z) + nb2(v3.w);
        }
        for (; i < total4; i += stride) {
            float4 v = __ldcs(cls4 + i);
            a0 += nb2(v.x) + nb2(v.y) + nb2(v.z) + nb2(v.w);
        }
        float v = (a0 + a1) + (a2 + a3);
        #pragma unroll
        for (int o = 16; o; o >>= 1) v += __shfl_down_sync(0xffffffffu, v, o);
        if (lane == 0) wsf[wrp] = v;
        __syncthreads();
        if (tid == 0) {
            float s = 0.f;
            #pragma unroll
            for (int k = 0; k < 8; k++) s += wsf[k];
            g_focal[blockIdx.x - BB] = (double)s * LN2;
        }
    } else {
        // ================= per-batch path (blocks 0..BB-1) =================
        const int b = blockIdx.x;
        const float* clsb = cls + (size_t)b * CC * HH * WW;

        for (int s = tid; s < HSZ; s += 256) { hkey[s] = HEMPTY; hval[s] = 0u; }
        if (tid == 0) s_last = -1;
        __syncthreads();
        if (tid < NN && gt_class[b * NN + tid] != -1) atomicMax(&s_last, tid);
        __syncthreads();

        // --- scatter gt into shared hash (max-dedup) ---
        if (tid < NN) {
            int clsv = gt_class[b * NN + tid];
            if (clsv != -1) {
                int ch = max(clsv, 0);
                const float* bx = gt_box + (b * NN + tid) * 4;
                float wv = bx[2] - bx[0];
                float hv = bx[3] - bx[1];
                int cx = (int)floorf(floorf(wv * 0.5f) * 0.25f);
                int cy = (int)floorf(floorf(hv * 0.5f) * 0.25f);
                const float ONE_V = 0.6065306597126334f;   // exp(-0.5)
                const float TWO_V = 0.36787944117144233f;  // exp(-1.0)
                bool interior = (cx >= 1) && (cy >= 1) && (cx + 1 < HH) && (cy + 1 < WW);
                #pragma unroll
                for (int k = 0; k < 9; k++) {
                    int dx = k / 3 - 1, dy = k % 3 - 1;
                    float vv;
                    if (dx == 0 && dy == 0) {
                        if (cx < 0 || cx >= HH || cy < 0 || cy >= WW) continue;
                        vv = 1.0f;
                    } else {
                        if (!interior) continue;
                        vv = (dx != 0 && dy != 0) ? TWO_V : ONE_V;
                    }
                    unsigned cell = (unsigned)(((ch * HH + cx + dx) * WW) + cy + dy);
                    unsigned slot = (cell * 2654435761u) & (HSZ - 1);
                    while (true) {
                        unsigned prev = atomicCAS(&hkey[slot], HEMPTY, cell);
                        if (prev == HEMPTY || prev == cell) {
                            atomicMax(&hval[slot], __float_as_uint(vv));
                            break;
                        }
                        slot = (slot + 1) & (HSZ - 1);
                    }
                }
            }
        }
        __syncthreads();

        // --- focal corrections at dedup'd cells ---
        float corr = 0.f;
        for (int s = tid; s < HSZ; s += 256) {
            unsigned cell = hkey[s];
            if (cell != HEMPTY) {
                float g = __uint_as_float(hval[s]);
                float p = clampp(clsb[cell]);
                float base = p * p * __logf(1.0f - p);
                float actual;
                if (g == 1.0f) {
                    float q = 1.0f - p, q2 = q * q;
                    actual = q2 * q2 * __logf(p);
                } else {
                    float q = 1.0f - g, q2 = q * q;
                    actual = q2 * q2 * base;
                }
                corr += actual - base;
            }
        }
        #pragma unroll
        for (int o = 16; o; o >>= 1) corr += __shfl_down_sync(0xffffffffu, corr, o);
        if (lane == 0) wsf[wrp] = corr;
        __syncthreads();
        if (tid == 0) {
            float s = 0.f;
            #pragma unroll
            for (int k = 0; k < 8; k++) s += wsf[k];
            g_corr[b] = s;
        }
        __syncthreads();

        // --- target: top-CANDK smallest cls in window of LAST valid kp ---
        int last = s_last;
        float sO = 0.f, sS = 0.f;
        int K = 0;
        if (last >= 0) {
            const float* bx = gt_box + (b * NN + last) * 4;
            float wv = bx[2] - bx[0];
            float hv = bx[3] - bx[1];
            int ch = max(gt_class[b * NN + last], 0);
            int cx = (int)floorf(floorf(wv * 0.5f) * 0.25f);
            int cy = (int)floorf(floorf(hv * 0.5f) * 0.25f);
            int w4 = (int)floorf(wv * 0.25f);
            int h4 = (int)floorf(hv * 0.25f);
            int left   = max((cx - (w4 >> 1)) >> 1, 0);   // >>1 == floor-div 2
            int right  = min((cx + (w4 >> 1)) >> 1, HH / 2);
            int top    = max((cy - (h4 >> 1)) >> 1, 0);
            int bottom = min((cy + (h4 >> 1)) >> 1, WW / 2);
            int wr = right - left, hc = bottom - top;
            int M = (wr > 0 && hc > 0) ? wr * hc : 0;
            K = min(CANDK, M);
            if (M > 0) {
                // window keys in REGISTERS: (valbits<<32 | flat_idx)
                unsigned long long rk[16];
                #pragma unroll
                for (int j = 0; j < 16; j++) {
                    int t = tid + j * 256;
                    if (t < M) {
                        int r = left + t / hc;
                        int c = top + t % hc;
                        float vv = clsb[(ch * HH + r) * WW + c];
                        rk[j] = (((unsigned long long)__float_as_uint(vv)) << 32)
                              | (unsigned)(r * WW + c);
                    } else {
                        rk[j] = ~0ull;
                    }
                }
                unsigned long long T = ~0ull;
                if (M > K) {
                    // radix-select Kth smallest; bits [16,32) always zero ->
                    // 6 digit passes (prefix <<= 16 after pass 3)
                    if (tid == 0) { s_prefix = 0ull; s_kth = K; }
                    __syncthreads();
                    const int digits[6] = {56, 48, 40, 32, 8, 0};
                    #pragma unroll
                    for (int pi = 0; pi < 6; pi++) {
                        int d = digits[pi];
                        hist[tid] = 0;
                        __syncthreads();
                        unsigned long long pfx = s_prefix;
                        int kth = s_kth;
                        #pragma unroll
                        for (int j = 0; j < 16; j++) {
                            bool valid = (tid + j * 256) < M;
                            unsigned long long key = rk[j];
                            bool act = valid && (pi == 0 || (key >> (d + 8)) == pfx);
                            int bin = act ? (int)((key >> d) & 255) : 256;
                            // warp-aggregate same-bin atomics
                            unsigned mset = __match_any_sync(0xffffffffu, bin);
                            if (act && lane == __ffs(mset) - 1)
                                atomicAdd(&hist[bin], __popc(mset));
                        }
                        __syncthreads();
                        // parallel 256-bin inclusive scan (thread tid owns bin tid)
                        int h0 = hist[tid];
                        int h = h0;
                        #pragma unroll
                        for (int o = 1; o < 32; o <<= 1) {
                            int n = __shfl_up_sync(0xffffffffu, h, o);
                            if (lane >= o) h += n;
                        }
                        if (lane == 31) wsum[wrp] = h;
                        __syncthreads();
                        if (tid < 8) {
                            int s = wsum[tid];
                            #pragma unroll
                            for (int o = 1; o < 8; o <<= 1) {
                                int n = __shfl_up_sync(0xffu, s, o);
                                if (tid >= o) s += n;
                            }
                            wsum[tid] = s;
                        }
                        __syncthreads();
                        int cum = h + (wrp ? wsum[wrp - 1] : 0);
                        if (cum - h0 < kth && kth <= cum) {   // exactly one thread
                            s_kth = kth - (cum - h0);
                            unsigned long long np = (pfx << 8) | (unsigned)tid;
                            if (pi == 3) np <<= 16;           // skip zero bits [16,32)
                            s_prefix = np;
                        }
                        __syncthreads();
                    }
                    T = s_prefix;
                }
                float cxf = wv * 0.5f * 0.25f;
                float cyf = hv * 0.5f * 0.25f;
                float off0 = cxf - floorf(cxf);
                float off1 = cyf - floorf(cyf);
                #pragma unroll
                for (int j = 0; j < 16; j++) {
                    bool valid = (tid + j * 256) < M;
                    if (valid && rk[j] <= T) {
                        unsigned idx = (unsigned)(rk[j] & 0xffffffffu);
                        int i2 = idx / WW, j2 = idx % WW;
                        float o0 = offp[((b * 2 + 0) * HH + i2) * WW + j2];
                        float o1 = offp[((b * 2 + 1) * HH + i2) * WW + j2];
                        float s0 = sizep[((b * 2 + 0) * HH + i2) * WW + j2];
                        float s1 = sizep[((b * 2 + 1) * HH + i2) * WW + j2];
                        sO += fabsf(o0 - off0) + fabsf(o1 - off1);
                        sS += fabsf(s0 - wv) + fabsf(s1 - hv);
                    }
                }
            }
        }
        #pragma unroll
        for (int o = 16; o; o >>= 1) {
            sO += __shfl_down_sync(0xffffffffu, sO, o);
            sS += __shfl_down_sync(0xffffffffu, sS, o);
        }
        __syncthreads();
        if (lane == 0) { wsf[wrp] = sO; wsd[wrp] = (double)sS; }
        __syncthreads();
        if (tid == 0) {
            float aO = 0.f, aS = 0.f;
            #pragma unroll
            for (int k = 0; k < 8; k++) { aO += wsf[k]; aS += (float)wsd[k]; }
            g_off[b] = aO;
            g_size[b] = aS;
            g_npos[b] = K;
        }
    }

    // ================= last-block combine (replaces finalize) =================
    __threadfence();
    __syncthreads();
    if (tid == 0) s_flag = (atomicAdd(&g_done, 1) == NBLK - 1);
    __syncthreads();
    if (s_flag) {
        __threadfence();
        double acc = 0.0;
        for (int i2 = tid; i2 < FBLK; i2 += 256) acc += g_focal[i2];
        #pragma unroll
        for (int o = 16; o; o >>= 1) acc += __shfl_down_sync(0xffffffffu, acc, o);
        if (lane == 0) wsd[wrp] = acc;
        __syncthreads();
        if (tid == 0) {
            double fsum = 0.0;
            #pragma unroll
            for (int k = 0; k < 8; k++) fsum += wsd[k];
            double corr = 0.0, offs = 0.0, szs = 0.0;
            int npos = 0;
            for (int b2 = 0; b2 < BB; b2++) {
                corr += (double)g_corr[b2];
                offs += (double)g_off[b2];
                szs  += (double)g_size[b2];
                npos += g_npos[b2];
            }
            double np = (double)max(npos, 1);
            double cls_loss = -(fsum + corr) / (double)(BB * HH * WW);
            out[0] = (float)(cls_loss + 0.1 * (szs / np) + (offs / np));
            g_done = 0;   // reset for next graph replay
        }
    }
}

extern "C" void kernel_launch(void* const* d_in, const int* in_sizes, int n_in,
                              void* d_out, int out_size) {
    const float* cls_pred    = (const float*)d_in[0];
    const float* offset_pred = (const float*)d_in[1];
    const float* size_pred   = (const float*)d_in[2];
    const float* gt_box      = (const float*)d_in[3];
    const int*   gt_class    = (const int*)d_in[4];
    float* out = (float*)d_out;
    (void)in_sizes; (void)n_in; (void)out_size;

    fused_kernel<<<NBLK, 256>>>((const float4*)cls_pred, cls_pred,
                                offset_pred, size_pred, gt_box, gt_class, out);
}

// round 5
// speedup vs baseline: 1.8077x; 1.1233x over previous
#include <cuda_runtime.h>

#define BB 16
#define CC 80
#define HH 128
#define WW 128
#define NN 50
#define CANDK 100
#define FBLK 1020
#define NBLK (FBLK + BB)
#define HSZ 1024
#define HEMPTY 0xFFFFFFFFu
#define KMAX 2048           // window is <=38x38 given input box ranges
#define LN2 0.6931471805599453

// Partials (every slot written unconditionally each launch) + done counter
// (zero at load; reset by the combining block each launch -> replay-safe).
__device__ double g_focal[FBLK];
__device__ float  g_corr[BB];
__device__ float  g_off[BB];
__device__ float  g_size[BB];
__device__ int    g_npos[BB];
__device__ int    g_done;

__device__ __forceinline__ float clampp(float x) {
    return fminf(fmaxf(x, 1e-4f), 0.9999f);
}
// p^2 * lg2(1-p): ln2 factored out once per block
__device__ __forceinline__ float nb2(float x) {
    float p = clampp(x);
    return p * p * __log2f(1.0f - p);
}

__global__ void __launch_bounds__(256, 7)
fused_kernel(const float4* __restrict__ cls4,
             const float* __restrict__ cls,
             const float* __restrict__ offp,
             const float* __restrict__ sizep,
             const float* __restrict__ gt_box,
             const int* __restrict__ gt_class,
             float* __restrict__ out) {
    extern __shared__ unsigned long long keys[];   // KMAX u64 = 16 KB dynamic
    __shared__ unsigned hkey[HSZ];
    __shared__ unsigned hval[HSZ];
    __shared__ int hist[256];
    __shared__ int wsum[8];
    __shared__ float wsf[8];
    __shared__ double wsd[8];
    __shared__ int s_last;
    __shared__ unsigned long long s_prefix;
    __shared__ int s_kth;
    __shared__ int s_flag;

    const int tid = threadIdx.x;
    const int lane = tid & 31, wrp = tid >> 5;

    if (blockIdx.x >= BB) {
        // ================= focal partial (blocks BB..NBLK-1) =================
        const int total4 = BB * CC * HH * WW / 4;
        const int stride = FBLK * 256;
        int i = (blockIdx.x - BB) * 256 + tid;
        float a0 = 0.f, a1 = 0.f, a2 = 0.f, a3 = 0.f;
        for (; i + 3 * stride < total4; i += 4 * stride) {
            float4 v0 = __ldcs(cls4 + i);
            float4 v1 = __ldcs(cls4 + i + stride);
            float4 v2 = __ldcs(cls4 + i + 2 * stride);
            float4 v3 = __ldcs(cls4 + i + 3 * stride);
            a0 += nb2(v0.x) + nb2(v0.y) + nb2(v0.z) + nb2(v0.w);
            a1 += nb2(v1.x) + nb2(v1.y) + nb2(v1.z) + nb2(v1.w);
            a2 += nb2(v2.x) + nb2(v2.y) + nb2(v2.z) + nb2(v2.w);
            a3 += nb2(v3.x) + nb2(v3.y) + nb2(v3.z) + nb2(v3.w);
        }
        for (; i < total4; i += stride) {
            float4 v = __ldcs(cls4 + i);
            a0 += nb2(v.x) + nb2(v.y) + nb2(v.z) + nb2(v.w);
        }
        float v = (a0 + a1) + (a2 + a3);
        #pragma unroll
        for (int o = 16; o; o >>= 1) v += __shfl_down_sync(0xffffffffu, v, o);
        if (lane == 0) wsf[wrp] = v;
        __syncthreads();
        if (tid == 0) {
            float s = 0.f;
            #pragma unroll
            for (int k = 0; k < 8; k++) s += wsf[k];
            g_focal[blockIdx.x - BB] = (double)s * LN2;
        }
    } else {
        // ================= per-batch path (blocks 0..BB-1) =================
        const int b = blockIdx.x;
        const float* clsb = cls + (size_t)b * CC * HH * WW;

        for (int s = tid; s < HSZ; s += 256) { hkey[s] = HEMPTY; hval[s] = 0u; }
        if (tid == 0) s_last = -1;
        __syncthreads();
        if (tid < NN && gt_class[b * NN + tid] != -1) atomicMax(&s_last, tid);
        __syncthreads();

        // --- scatter gt into shared hash (max-dedup) ---
        if (tid < NN) {
            int clsv = gt_class[b * NN + tid];
            if (clsv != -1) {
                int ch = max(clsv, 0);
                const float* bx = gt_box + (b * NN + tid) * 4;
                float wv = bx[2] - bx[0];
                float hv = bx[3] - bx[1];
                int cx = (int)floorf(floorf(wv * 0.5f) * 0.25f);
                int cy = (int)floorf(floorf(hv * 0.5f) * 0.25f);
                const float ONE_V = 0.6065306597126334f;   // exp(-0.5)
                const float TWO_V = 0.36787944117144233f;  // exp(-1.0)
                bool interior = (cx >= 1) && (cy >= 1) && (cx + 1 < HH) && (cy + 1 < WW);
                #pragma unroll
                for (int k = 0; k < 9; k++) {
                    int dx = k / 3 - 1, dy = k % 3 - 1;
                    float vv;
                    if (dx == 0 && dy == 0) {
                        if (cx < 0 || cx >= HH || cy < 0 || cy >= WW) continue;
                        vv = 1.0f;
                    } else {
                        if (!interior) continue;
                        vv = (dx != 0 && dy != 0) ? TWO_V : ONE_V;
                    }
                    unsigned cell = (unsigned)(((ch * HH + cx + dx) * WW) + cy + dy);
                    unsigned slot = (cell * 2654435761u) & (HSZ - 1);
                    while (true) {
                        unsigned prev = atomicCAS(&hkey[slot], HEMPTY, cell);
                        if (prev == HEMPTY || prev == cell) {
                            atomicMax(&hval[slot], __float_as_uint(vv));
                            break;
                        }
                        slot = (slot + 1) & (HSZ - 1);
                    }
                }
            }
        }
        __syncthreads();

        // --- focal corrections at dedup'd cells ---
        float corr = 0.f;
        for (int s = tid; s < HSZ; s += 256) {
            unsigned cell = hkey[s];
            if (cell != HEMPTY) {
                float g = __uint_as_float(hval[s]);
                float p = clampp(clsb[cell]);
                float base = p * p * __logf(1.0f - p);
                float actual;
                if (g == 1.0f) {
                    float q = 1.0f - p, q2 = q * q;
                    actual = q2 * q2 * __logf(p);
                } else {
                    float q = 1.0f - g, q2 = q * q;
                    actual = q2 * q2 * base;
                }
                corr += actual - base;
            }
        }
        #pragma unroll
        for (int o = 16; o; o >>= 1) corr += __shfl_down_sync(0xffffffffu, corr, o);
        if (lane == 0) wsf[wrp] = corr;
        __syncthreads();
        if (tid == 0) {
            float s = 0.f;
            #pragma unroll
            for (int k = 0; k < 8; k++) s += wsf[k];
            g_corr[b] = s;
        }
        __syncthreads();

        // --- target: top-CANDK smallest cls in window of LAST valid kp ---
        int last = s_last;
        float sO = 0.f, sS = 0.f;
        int K = 0;
        if (last >= 0) {
            const float* bx = gt_box + (b * NN + last) * 4;
            float wv = bx[2] - bx[0];
            float hv = bx[3] - bx[1];
            int ch = max(gt_class[b * NN + last], 0);
            int cx = (int)floorf(floorf(wv * 0.5f) * 0.25f);
            int cy = (int)floorf(floorf(hv * 0.5f) * 0.25f);
            int w4 = (int)floorf(wv * 0.25f);
            int h4 = (int)floorf(hv * 0.25f);
            int left   = max((cx - (w4 >> 1)) >> 1, 0);   // >>1 == floor-div 2
            int right  = min((cx + (w4 >> 1)) >> 1, HH / 2);
            int top    = max((cy - (h4 >> 1)) >> 1, 0);
            int bottom = min((cy + (h4 >> 1)) >> 1, WW / 2);
            int wr = right - left, hc = bottom - top;
            int M = (wr > 0 && hc > 0) ? wr * hc : 0;
            M = min(M, KMAX);   // guaranteed by input ranges; hard safety clamp
            K = min(CANDK, M);
            if (M > 0) {
                // packed (valbits<<32 | flat_idx) in shared; asc == jax order
                for (int t = tid; t < M; t += 256) {
                    int r = left + t / hc;
                    int c = top + t % hc;
                    float vv = clsb[(ch * HH + r) * WW + c];
                    keys[t] = (((unsigned long long)__float_as_uint(vv)) << 32)
                            | (unsigned)(r * WW + c);
                }
                __syncthreads();
                unsigned long long T = ~0ull;
                if (M > K) {
                    // radix-select Kth smallest; key bits [16,32) are always 0
                    // -> 6 digit passes (prefix <<= 16 after pass 3)
                    if (tid == 0) { s_prefix = 0ull; s_kth = K; }
                    __syncthreads();
                    const int Mr = (M + 255) & ~255;   // uniform trip count
                    const int digits[6] = {56, 48, 40, 32, 8, 0};
                    #pragma unroll
                    for (int pi = 0; pi < 6; pi++) {
                        int d = digits[pi];
                        hist[tid] = 0;
                        __syncthreads();
                        unsigned long long pfx = s_prefix;
                        int kth = s_kth;
                        for (int i = tid; i < Mr; i += 256) {
                            bool valid = i < M;
                            unsigned long long key = valid ? keys[i] : 0ull;
                            bool act = valid && (pi == 0 || (key >> (d + 8)) == pfx);
                            int bin = act ? (int)((key >> d) & 255) : 256;
                            unsigned mset = __match_any_sync(0xffffffffu, bin);
                            if (act && lane == (__ffs(mset) - 1))
                                atomicAdd(&hist[bin], __popc(mset));
                        }
                        __syncthreads();
                        // parallel 256-bin inclusive scan (thread tid = bin tid)
                        int h0 = hist[tid];
                        int h = h0;
                        #pragma unroll
                        for (int o = 1; o < 32; o <<= 1) {
                            int n = __shfl_up_sync(0xffffffffu, h, o);
                            if (lane >= o) h += n;
                        }
                        if (lane == 31) wsum[wrp] = h;
                        __syncthreads();
                        if (tid < 8) {
                            int s = wsum[tid];
                            #pragma unroll
                            for (int o = 1; o < 8; o <<= 1) {
                                int n = __shfl_up_sync(0xffu, s, o);
                                if (tid >= o) s += n;
                            }
                            wsum[tid] = s;
                        }
                        __syncthreads();
                        int cum = h + (wrp ? wsum[wrp - 1] : 0);
                        if (cum - h0 < kth && kth <= cum) {   // exactly one thread
                            s_kth = kth - (cum - h0);
                            unsigned long long np = (pfx << 8) | (unsigned)tid;
                            if (pi == 3) np <<= 16;           // skip zero bits
                            s_prefix = np;
                        }
                        __syncthreads();
                    }
                    T = s_prefix;
                }
                float cxf = wv * 0.5f * 0.25f;
                float cyf = hv * 0.5f * 0.25f;
                float off0 = cxf - floorf(cxf);
                float off1 = cyf - floorf(cyf);
                for (int t = tid; t < M; t += 256) {
                    if (keys[t] <= T) {
                        unsigned idx = (unsigned)(keys[t] & 0xffffffffu);
                        int i2 = idx / WW, j2 = idx % WW;
                        float o0 = offp[((b * 2 + 0) * HH + i2) * WW + j2];
                        float o1 = offp[((b * 2 + 1) * HH + i2) * WW + j2];
                        float s0 = sizep[((b * 2 + 0) * HH + i2) * WW + j2];
                        float s1 = sizep[((b * 2 + 1) * HH + i2) * WW + j2];
                        sO += fabsf(o0 - off0) + fabsf(o1 - off1);
                        sS += fabsf(s0 - wv) + fabsf(s1 - hv);
                    }
                }
            }
        }
        #pragma unroll
        for (int o = 16; o; o >>= 1) {
            sO += __shfl_down_sync(0xffffffffu, sO, o);
            sS += __shfl_down_sync(0xffffffffu, sS, o);
        }
        __syncthreads();
        if (lane == 0) { wsf[wrp] = sO; wsd[wrp] = (double)sS; }
        __syncthreads();
        if (tid == 0) {
            float aO = 0.f, aS = 0.f;
            #pragma unroll
            for (int k = 0; k < 8; k++) { aO += wsf[k]; aS += (float)wsd[k]; }
            g_off[b] = aO;
            g_size[b] = aS;
            g_npos[b] = K;
        }
    }

    // ================= last-block combine =================
    __threadfence();
    __syncthreads();
    if (tid == 0) s_flag = (atomicAdd(&g_done, 1) == NBLK - 1);
    __syncthreads();
    if (s_flag) {
        __threadfence();
        double acc = 0.0;
        for (int i2 = tid; i2 < FBLK; i2 += 256) acc += g_focal[i2];
        #pragma unroll
        for (int o = 16; o; o >>= 1) acc += __shfl_down_sync(0xffffffffu, acc, o);
        if (lane == 0) wsd[wrp] = acc;
        __syncthreads();
        if (tid == 0) {
            double fsum = 0.0;
            #pragma unroll
            for (int k = 0; k < 8; k++) fsum += wsd[k];
            double corr = 0.0, offs = 0.0, szs = 0.0;
            int npos = 0;
            for (int b2 = 0; b2 < BB; b2++) {
                corr += (double)g_corr[b2];
                offs += (double)g_off[b2];
                szs  += (double)g_size[b2];
                npos += g_npos[b2];
            }
            double np = (double)max(npos, 1);
            double cls_loss = -(fsum + corr) / (double)(BB * HH * WW);
            out[0] = (float)(cls_loss + 0.1 * (szs / np) + (offs / np));
            g_done = 0;   // reset for next graph replay
        }
    }
}

extern "C" void kernel_launch(void* const* d_in, const int* in_sizes, int n_in,
                              void* d_out, int out_size) {
    const float* cls_pred    = (const float*)d_in[0];
    const float* offset_pred = (const float*)d_in[1];
    const float* size_pred   = (const float*)d_in[2];
    const float* gt_box      = (const float*)d_in[3];
    const int*   gt_class    = (const int*)d_in[4];
    float* out = (float*)d_out;
    (void)in_sizes; (void)n_in; (void)out_size;

    fused_kernel<<<NBLK, 256, KMAX * sizeof(unsigned long long)>>>(
        (const float4*)cls_pred, cls_pred,
        offset_pred, size_pred, gt_box, gt_class, out);
}

// round 6
// speedup vs baseline: 1.9048x; 1.0537x over previous
#include <cuda_runtime.h>

#define BB 16
#define CC 80
#define HH 128
#define WW 128
#define NN 50
#define CANDK 100
#define TPB 512
#define FBLK 576
#define NBLK (FBLK + BB)
#define HSZ 1024
#define HEMPTY 0xFFFFFFFFu
#define KMAX 2048           // window <= 38x38 given input box ranges
#define LN2 0.6931471805599453

// Partials (every slot written unconditionally each launch) + done counter
// (zero at load; reset by the combining block each launch -> replay-safe).
__device__ double g_focal[FBLK];
__device__ float  g_corr[BB];
__device__ float  g_off[BB];
__device__ float  g_size[BB];
__device__ int    g_npos[BB];
__device__ int    g_done;

__device__ __forceinline__ float clampp(float x) {
    return fminf(fmaxf(x, 1e-4f), 0.9999f);
}
// p^2 * lg2(1-p): ln2 factored out once per block
__device__ __forceinline__ float nb2(float x) {
    float p = clampp(x);
    return p * p * __log2f(1.0f - p);
}

__global__ void __launch_bounds__(TPB, 4)
fused_kernel(const float4* __restrict__ cls4,
             const float* __restrict__ cls,
             const float* __restrict__ offp,
             const float* __restrict__ sizep,
             const float* __restrict__ gt_box,
             const int* __restrict__ gt_class,
             float* __restrict__ out) {
    __shared__ unsigned keys_v[KMAX];        // 8 KB (value bits)
    __shared__ unsigned short keys_i[KMAX];  // 4 KB (flat index, 14 bits)
    __shared__ unsigned hkey[HSZ];           // 4 KB
    __shared__ unsigned hval[HSZ];           // 4 KB
    __shared__ int hist[256];
    __shared__ int wsum[8];
    __shared__ float wsf[16];
    __shared__ double wsd[16];
    __shared__ int s_last;
    __shared__ unsigned s_pfx;
    __shared__ int s_kth;
    __shared__ int s_eq;
    __shared__ int s_flag;

    const int tid = threadIdx.x;
    const int lane = tid & 31, wrp = tid >> 5;

    if (blockIdx.x >= BB) {
        // ================= focal partial (blocks BB..NBLK-1) =================
        const int total4 = BB * CC * HH * WW / 4;
        const int stride = FBLK * TPB;
        int i = (blockIdx.x - BB) * TPB + tid;
        float a0 = 0.f, a1 = 0.f, a2 = 0.f, a3 = 0.f;
        for (; i + 3 * stride < total4; i += 4 * stride) {
            float4 v0 = cls4[i];
            float4 v1 = cls4[i + stride];
            float4 v2 = cls4[i + 2 * stride];
            float4 v3 = cls4[i + 3 * stride];
            a0 += nb2(v0.x) + nb2(v0.y) + nb2(v0.z) + nb2(v0.w);
            a1 += nb2(v1.x) + nb2(v1.y) + nb2(v1.z) + nb2(v1.w);
            a2 += nb2(v2.x) + nb2(v2.y) + nb2(v2.z) + nb2(v2.w);
            a3 += nb2(v3.x) + nb2(v3.y) + nb2(v3.z) + nb2(v3.w);
        }
        for (; i < total4; i += stride) {
            float4 v = cls4[i];
            a0 += nb2(v.x) + nb2(v.y) + nb2(v.z) + nb2(v.w);
        }
        float v = (a0 + a1) + (a2 + a3);
        #pragma unroll
        for (int o = 16; o; o >>= 1) v += __shfl_down_sync(0xffffffffu, v, o);
        if (lane == 0) wsf[wrp] = v;
        __syncthreads();
        if (tid == 0) {
            float s = 0.f;
            #pragma unroll
            for (int k = 0; k < 16; k++) s += wsf[k];
            g_focal[blockIdx.x - BB] = (double)s * LN2;
        }
    } else {
        // ================= per-batch path (blocks 0..BB-1) =================
        const int b = blockIdx.x;
        const float* clsb = cls + (size_t)b * CC * HH * WW;

        for (int s = tid; s < HSZ; s += TPB) { hkey[s] = HEMPTY; hval[s] = 0u; }
        if (tid == 0) s_last = -1;
        __syncthreads();
        if (tid < NN && gt_class[b * NN + tid] != -1) atomicMax(&s_last, tid);
        __syncthreads();

        // --- scatter gt into shared hash (max-dedup) ---
        if (tid < NN) {
            int clsv = gt_class[b * NN + tid];
            if (clsv != -1) {
                int ch = max(clsv, 0);
                const float* bx = gt_box + (b * NN + tid) * 4;
                float wv = bx[2] - bx[0];
                float hv = bx[3] - bx[1];
                int cx = (int)floorf(floorf(wv * 0.5f) * 0.25f);
                int cy = (int)floorf(floorf(hv * 0.5f) * 0.25f);
                const float ONE_V = 0.6065306597126334f;   // exp(-0.5)
                const float TWO_V = 0.36787944117144233f;  // exp(-1.0)
                bool interior = (cx >= 1) && (cy >= 1) && (cx + 1 < HH) && (cy + 1 < WW);
                #pragma unroll
                for (int k = 0; k < 9; k++) {
                    int dx = k / 3 - 1, dy = k % 3 - 1;
                    float vv;
                    if (dx == 0 && dy == 0) {
                        if (cx < 0 || cx >= HH || cy < 0 || cy >= WW) continue;
                        vv = 1.0f;
                    } else {
                        if (!interior) continue;
                        vv = (dx != 0 && dy != 0) ? TWO_V : ONE_V;
                    }
                    unsigned cell = (unsigned)(((ch * HH + cx + dx) * WW) + cy + dy);
                    unsigned slot = (cell * 2654435761u) & (HSZ - 1);
                    while (true) {
                        unsigned prev = atomicCAS(&hkey[slot], HEMPTY, cell);
                        if (prev == HEMPTY || prev == cell) {
                            atomicMax(&hval[slot], __float_as_uint(vv));
                            break;
                        }
                        slot = (slot + 1) & (HSZ - 1);
                    }
                }
            }
        }
        __syncthreads();

        // --- focal corrections at dedup'd cells ---
        float corr = 0.f;
        for (int s = tid; s < HSZ; s += TPB) {
            unsigned cell = hkey[s];
            if (cell != HEMPTY) {
                float g = __uint_as_float(hval[s]);
                float p = clampp(clsb[cell]);
                float base = p * p * __logf(1.0f - p);
                float actual;
                if (g == 1.0f) {
                    float q = 1.0f - p, q2 = q * q;
                    actual = q2 * q2 * __logf(p);
                } else {
                    float q = 1.0f - g, q2 = q * q;
                    actual = q2 * q2 * base;
                }
                corr += actual - base;
            }
        }
        #pragma unroll
        for (int o = 16; o; o >>= 1) corr += __shfl_down_sync(0xffffffffu, corr, o);
        if (lane == 0) wsf[wrp] = corr;
        __syncthreads();
        if (tid == 0) {
            float s = 0.f;
            #pragma unroll
            for (int k = 0; k < 16; k++) s += wsf[k];
            g_corr[b] = s;
        }
        __syncthreads();

        // --- target: top-CANDK smallest cls in window of LAST valid kp ---
        int last = s_last;
        float sO = 0.f, sS = 0.f;
        int K = 0;
        if (last >= 0) {
            const float* bx = gt_box + (b * NN + last) * 4;
            float wv = bx[2] - bx[0];
            float hv = bx[3] - bx[1];
            int ch = max(gt_class[b * NN + last], 0);
            int cx = (int)floorf(floorf(wv * 0.5f) * 0.25f);
            int cy = (int)floorf(floorf(hv * 0.5f) * 0.25f);
            int w4 = (int)floorf(wv * 0.25f);
            int h4 = (int)floorf(hv * 0.25f);
            int left   = max((cx - (w4 >> 1)) >> 1, 0);   // >>1 == floor-div 2
            int right  = min((cx + (w4 >> 1)) >> 1, HH / 2);
            int top    = max((cy - (h4 >> 1)) >> 1, 0);
            int bottom = min((cy + (h4 >> 1)) >> 1, WW / 2);
            int wr = right - left, hc = bottom - top;
            int M = (wr > 0 && hc > 0) ? wr * hc : 0;
            M = min(M, KMAX);   // guaranteed by input ranges; hard safety clamp
            K = min(CANDK, M);
            if (M > 0) {
                // value bits + flat index, padded to a 512 multiple
                int Mr = (M + TPB - 1) & ~(TPB - 1);
                for (int t = tid; t < M; t += TPB) {
                    int r = left + t / hc;
                    int c = top + t % hc;
                    float vv = clsb[(ch * HH + r) * WW + c];
                    keys_v[t] = __float_as_uint(vv);   // positive floats: asc bits == asc value
                    keys_i[t] = (unsigned short)(r * WW + c);
                }
                for (int t = M + tid; t < Mr; t += TPB) keys_v[t] = 0xFFFFFFFFu;
                __syncthreads();

                unsigned V = 0xFFFFFFFFu;     // M <= K: select all
                unsigned Ti = 0xFFFFu;        // inclusive index threshold at v==V
                if (M > K) {
                    // ---- 4-pass radix-select of Kth smallest VALUE ----
                    if (tid == 0) { s_pfx = 0u; s_kth = K; }
                    __syncthreads();
                    #pragma unroll
                    for (int pi = 0; pi < 4; pi++) {
                        const int d = 24 - 8 * pi;
                        if (tid < 256) hist[tid] = 0;
                        __syncthreads();
                        unsigned pfx = s_pfx;
                        int kth = s_kth;
                        for (int i = tid; i < Mr; i += TPB) {
                            unsigned v = keys_v[i];
                            if (pi == 0 || (v >> (d + 8)) == pfx)
                                atomicAdd(&hist[(v >> d) & 255], 1);
                        }
                        __syncthreads();
                        if (tid < 256) {   // warps 0-7 own the 256 bins
                            int h0 = hist[tid];
                            int h = h0;
                            #pragma unroll
                            for (int o = 1; o < 32; o <<= 1) {
                                int n = __shfl_up_sync(0xffffffffu, h, o);
                                if (lane >= o) h += n;
                            }
                            if (lane == 31) wsum[wrp] = h;
                            __syncwarp();
                        }
                        __syncthreads();
                        if (tid < 8) {
                            int s = wsum[tid];
                            #pragma unroll
                            for (int o = 1; o < 8; o <<= 1) {
                                int n = __shfl_up_sync(0xffu, s, o);
                                if (tid >= o) s += n;
                            }
                            wsum[tid] = s;
                        }
                        __syncthreads();
                        if (tid < 256) {
                            int h0 = hist[tid];
                            // recompute inclusive within-warp (cheap) via exclusive base
                            int h = h0;
                            #pragma unroll
                            for (int o = 1; o < 32; o <<= 1) {
                                int n = __shfl_up_sync(0xffffffffu, h, o);
                                if (lane >= o) h += n;
                            }
                            int cum = h + (wrp ? wsum[wrp - 1] : 0);
                            unsigned pfx2 = s_pfx;  // unchanged since snapshot
                            int kth2 = kth;
                            if (cum - h0 < kth2 && kth2 <= cum) {  // one thread
                                s_kth = kth2 - (cum - h0);
                                s_pfx = (pfx2 << 8) | (unsigned)tid;
                                if (pi == 3) s_eq = h0;
                            }
                        }
                        __syncthreads();
                    }
                    V = s_pfx;
                    int needed = s_kth, eqc = s_eq;
                    if (needed < eqc) {
                        // ---- rare: tie-break on index (2x7-bit radix) ----
                        if (tid == 0) s_pfx = 0u;
                        __syncthreads();
                        #pragma unroll
                        for (int pi = 0; pi < 2; pi++) {
                            const int d = 7 - 7 * pi;
                            if (tid < 128) hist[tid] = 0;
                            __syncthreads();
                            unsigned pfx = s_pfx;
                            int kth = s_kth;
                            for (int i = tid; i < Mr; i += TPB) {
                                if (keys_v[i] == V) {
                                    unsigned ix = keys_i[i];
                                    if (pi == 0 || (ix >> (d + 7)) == pfx)
                                        atomicAdd(&hist[(ix >> d) & 127], 1);
                                }
                            }
                            __syncthreads();
                            if (tid < 128) {
                                int h0 = hist[tid];
                                int h = h0;
                                #pragma unroll
                                for (int o = 1; o < 32; o <<= 1) {
                                    int n = __shfl_up_sync(0xffffffffu, h, o);
                                    if (lane >= o) h += n;
                                }
                                if (lane == 31) wsum[wrp] = h;
                                __syncwarp();
                            }
                            __syncthreads();
                            if (tid < 4) {
                                int s = wsum[tid];
                                #pragma unroll
                                for (int o = 1; o < 4; o <<= 1) {
                                    int n = __shfl_up_sync(0xfu, s, o);
                                    if (tid >= o) s += n;
                                }
                                wsum[tid] = s;
                            }
                            __syncthreads();
                            if (tid < 128) {
                                int h0 = hist[tid];
                                int h = h0;
                                #pragma unroll
                                for (int o = 1; o < 32; o <<= 1) {
                                    int n = __shfl_up_sync(0xffffffffu, h, o);
                                    if (lane >= o) h += n;
                                }
                                int cum = h + (wrp ? wsum[wrp - 1] : 0);
                                if (cum - h0 < kth && kth <= cum) {
                                    s_kth = kth - (cum - h0);
                                    s_pfx = (s_pfx << 7) | (unsigned)tid;
                                }
                            }
                            __syncthreads();
                        }
                        Ti = s_pfx;   // include idx <= Ti among v==V
                    }
                }

                float cxf = wv * 0.5f * 0.25f;
                float cyf = hv * 0.5f * 0.25f;
                float off0 = cxf - floorf(cxf);
                float off1 = cyf - floorf(cyf);
                for (int t = tid; t < M; t += TPB) {
                    unsigned v = keys_v[t];
                    unsigned ix = keys_i[t];
                    if (v < V || (v == V && ix <= Ti)) {
                        int i2 = ix / WW, j2 = ix % WW;
                        float o0 = offp[((b * 2 + 0) * HH + i2) * WW + j2];
                        float o1 = offp[((b * 2 + 1) * HH + i2) * WW + j2];
                        float s0 = sizep[((b * 2 + 0) * HH + i2) * WW + j2];
                        float s1 = sizep[((b * 2 + 1) * HH + i2) * WW + j2];
                        sO += fabsf(o0 - off0) + fabsf(o1 - off1);
                        sS += fabsf(s0 - wv) + fabsf(s1 - hv);
                    }
                }
            }
        }
        #pragma unroll
        for (int o = 16; o; o >>= 1) {
            sO += __shfl_down_sync(0xffffffffu, sO, o);
            sS += __shfl_down_sync(0xffffffffu, sS, o);
        }
        __syncthreads();
        if (lane == 0) { wsf[wrp] = sO; wsd[wrp] = (double)sS; }
        __syncthreads();
        if (tid == 0) {
            float aO = 0.f, aS = 0.f;
            #pragma unroll
            for (int k = 0; k < 16; k++) { aO += wsf[k]; aS += (float)wsd[k]; }
            g_off[b] = aO;
            g_size[b] = aS;
            g_npos[b] = K;
        }
    }

    // ================= last-block combine =================
    __threadfence();
    __syncthreads();
    if (tid == 0) s_flag = (atomicAdd(&g_done, 1) == NBLK - 1);
    __syncthreads();
    if (s_flag) {
        __threadfence();
        double acc = 0.0;
        for (int i2 = tid; i2 < FBLK; i2 += TPB) acc += g_focal[i2];
        #pragma unroll
        for (int o = 16; o; o >>= 1) acc += __shfl_down_sync(0xffffffffu, acc, o);
        if (lane == 0) wsd[wrp] = acc;
        __syncthreads();
        if (tid == 0) {
            double fsum = 0.0;
            #pragma unroll
            for (int k = 0; k < 16; k++) fsum += wsd[k];
            double corr = 0.0, offs = 0.0, szs = 0.0;
            int npos = 0;
            for (int b2 = 0; b2 < BB; b2++) {
                corr += (double)g_corr[b2];
                offs += (double)g_off[b2];
                szs  += (double)g_size[b2];
                npos += g_npos[b2];
            }
            double np = (double)max(npos, 1);
            double cls_loss = -(fsum + corr) / (double)(BB * HH * WW);
            out[0] = (float)(cls_loss + 0.1 * (szs / np) + (offs / np));
            g_done = 0;   // reset for next graph replay
        }
    }
}

extern "C" void kernel_launch(void* const* d_in, const int* in_sizes, int n_in,
                              void* d_out, int out_size) {
    const float* cls_pred    = (const float*)d_in[0];
    const float* offset_pred = (const float*)d_in[1];
    const float* size_pred   = (const float*)d_in[2];
    const float* gt_box      = (const float*)d_in[3];
    const int*   gt_class    = (const int*)d_in[4];
    float* out = (float*)d_out;
    (void)in_sizes; (void)n_in; (void)out_size;

    fused_kernel<<<NBLK, TPB>>>((const float4*)cls_pred, cls_pred,
                                offset_pred, size_pred, gt_box, gt_class, out);
}

// round 7
// speedup vs baseline: 2.1236x; 1.1149x over previous
#include <cuda_runtime.h>

#define BB 16
#define CC 80
#define HH 128
#define WW 128
#define NN 50
#define CANDK 100
#define TPB 512
#define NBATCH 32
#define FBLK 560
#define NBLK (FBLK + NBATCH)    // 592 = 148 SMs * 4 blocks
#define HSZ 1024
#define HEMPTY 0xFFFFFFFFu
#define KARR 1536               // window <= 37x37 = 1369, rounded to TPB mult
#define LN2 0.6931471805599453

// Partials (each slot written unconditionally every launch) + done counter
// (zero at load; reset by the combining block each launch -> replay-safe).
__device__ double g_focal[FBLK];
__device__ float  g_corr[BB];
__device__ float  g_off[BB];
__device__ float  g_size[BB];
__device__ int    g_npos[BB];
__device__ int    g_done;

__device__ __forceinline__ float clampp(float x) {
    return fminf(fmaxf(x, 1e-4f), 0.9999f);
}
// p^2 * lg2(1-p): ln2 factored out once per block
__device__ __forceinline__ float nb2(float x) {
    float p = clampp(x);
    return p * p * __log2f(1.0f - p);
}

union SmemU {
    struct { unsigned hkey[HSZ]; unsigned hval[HSZ]; } a;              // 8 KB
    struct {
        unsigned keys_v[KARR];        // value bits (positive floats)
        unsigned short keys_i[KARR];  // flat 14-bit index
        float o0[KARR], o1[KARR], s0[KARR], s1[KARR];  // prefetched preds
    } b;                                                               // ~34 KB
};

__global__ void __launch_bounds__(TPB, 4)
fused_kernel(const float4* __restrict__ cls4,
             const float* __restrict__ cls,
             const float* __restrict__ offp,
             const float* __restrict__ sizep,
             const float* __restrict__ gt_box,
             const int* __restrict__ gt_class,
             float* __restrict__ out) {
    __shared__ SmemU u;
    __shared__ int hist[256];
    __shared__ int wsum[16];
    __shared__ float wsf[16];
    __shared__ double wsd[16];
    __shared__ float s_w[NN], s_h[NN];
    __shared__ int s_ch[NN];
    __shared__ int s_last;
    __shared__ unsigned s_pfx;
    __shared__ int s_kth;
    __shared__ int s_eq;
    __shared__ int s_flag;

    const int tid = threadIdx.x;
    const int lane = tid & 31, wrp = tid >> 5;

    if (blockIdx.x >= NBATCH) {
        // ================= focal partial (blocks 32..591) =================
        const int total4 = BB * CC * HH * WW / 4;
        const int stride = FBLK * TPB;
        int i = (blockIdx.x - NBATCH) * TPB + tid;
        float a0 = 0.f, a1 = 0.f, a2 = 0.f, a3 = 0.f;
        for (; i + 3 * stride < total4; i += 4 * stride) {
            float4 v0 = cls4[i];
            float4 v1 = cls4[i + stride];
            float4 v2 = cls4[i + 2 * stride];
            float4 v3 = cls4[i + 3 * stride];
            a0 += nb2(v0.x) + nb2(v0.y) + nb2(v0.z) + nb2(v0.w);
            a1 += nb2(v1.x) + nb2(v1.y) + nb2(v1.z) + nb2(v1.w);
            a2 += nb2(v2.x) + nb2(v2.y) + nb2(v2.z) + nb2(v2.w);
            a3 += nb2(v3.x) + nb2(v3.y) + nb2(v3.z) + nb2(v3.w);
        }
        for (; i < total4; i += stride) {
            float4 v = cls4[i];
            a0 += nb2(v.x) + nb2(v.y) + nb2(v.z) + nb2(v.w);
        }
        float v = (a0 + a1) + (a2 + a3);
        #pragma unroll
        for (int o = 16; o; o >>= 1) v += __shfl_down_sync(0xffffffffu, v, o);
        if (lane == 0) wsf[wrp] = v;
        __syncthreads();
        if (tid == 0) {
            float s = 0.f;
            #pragma unroll
            for (int k = 0; k < 16; k++) s += wsf[k];
            g_focal[blockIdx.x - NBATCH] = (double)s * LN2;
        }
    } else if (blockIdx.x < BB) {
        // ========== type A: gt hash-dedup + focal corrections ==========
        const int b = blockIdx.x;
        const float* clsb = cls + (size_t)b * CC * HH * WW;

        for (int s = tid; s < HSZ; s += TPB) { u.a.hkey[s] = HEMPTY; u.a.hval[s] = 0u; }
        __syncthreads();

        if (tid < NN) {
            int clsv = gt_class[b * NN + tid];
            float4 bx = ((const float4*)gt_box)[b * NN + tid];
            if (clsv != -1) {
                int ch = max(clsv, 0);
                float wv = bx.z - bx.x;
                float hv = bx.w - bx.y;
                int cx = (int)floorf(floorf(wv * 0.5f) * 0.25f);
                int cy = (int)floorf(floorf(hv * 0.5f) * 0.25f);
                const float ONE_V = 0.6065306597126334f;   // exp(-0.5)
                const float TWO_V = 0.36787944117144233f;  // exp(-1.0)
                bool interior = (cx >= 1) && (cy >= 1) && (cx + 1 < HH) && (cy + 1 < WW);
                #pragma unroll
                for (int k = 0; k < 9; k++) {
                    int dx = k / 3 - 1, dy = k % 3 - 1;
                    float vv;
                    if (dx == 0 && dy == 0) {
                        if (cx < 0 || cx >= HH || cy < 0 || cy >= WW) continue;
                        vv = 1.0f;
                    } else {
                        if (!interior) continue;
                        vv = (dx != 0 && dy != 0) ? TWO_V : ONE_V;
                    }
                    unsigned cell = (unsigned)(((ch * HH + cx + dx) * WW) + cy + dy);
                    unsigned slot = (cell * 2654435761u) & (HSZ - 1);
                    while (true) {
                        unsigned prev = atomicCAS(&u.a.hkey[slot], HEMPTY, cell);
                        if (prev == HEMPTY || prev == cell) {
                            atomicMax(&u.a.hval[slot], __float_as_uint(vv));
                            break;
                        }
                        slot = (slot + 1) & (HSZ - 1);
                    }
                }
            }
        }
        __syncthreads();

        float corr = 0.f;
        for (int s = tid; s < HSZ; s += TPB) {
            unsigned cell = u.a.hkey[s];
            if (cell != HEMPTY) {
                float g = __uint_as_float(u.a.hval[s]);
                float p = clampp(clsb[cell]);
                float base = p * p * __logf(1.0f - p);
                float actual;
                if (g == 1.0f) {
                    float q = 1.0f - p, q2 = q * q;
                    actual = q2 * q2 * __logf(p);
                } else {
                    float q = 1.0f - g, q2 = q * q;
                    actual = q2 * q2 * base;
                }
                corr += actual - base;
            }
        }
        #pragma unroll
        for (int o = 16; o; o >>= 1) corr += __shfl_down_sync(0xffffffffu, corr, o);
        if (lane == 0) wsf[wrp] = corr;
        __syncthreads();
        if (tid == 0) {
            float s = 0.f;
            #pragma unroll
            for (int k = 0; k < 16; k++) s += wsf[k];
            g_corr[b] = s;
        }
    } else {
        // ========== type B: top-CANDK select + offset/size loss ==========
        const int b = blockIdx.x - BB;
        const float* clsb = cls + (size_t)b * CC * HH * WW;

        if (tid == 0) s_last = -1;
        __syncthreads();
        if (tid < NN) {
            int clsv = gt_class[b * NN + tid];
            float4 bx = ((const float4*)gt_box)[b * NN + tid];
            s_w[tid] = bx.z - bx.x;
            s_h[tid] = bx.w - bx.y;
            s_ch[tid] = max(clsv, 0);
            if (clsv != -1) atomicMax(&s_last, tid);
        }
        __syncthreads();

        int last = s_last;
        float sO = 0.f, sS = 0.f;
        int K = 0;
        float wv = 0.f, hv = 0.f;
        if (last >= 0) {
            wv = s_w[last];
            hv = s_h[last];
            int ch = s_ch[last];
            int cx = (int)floorf(floorf(wv * 0.5f) * 0.25f);
            int cy = (int)floorf(floorf(hv * 0.5f) * 0.25f);
            int w4 = (int)floorf(wv * 0.25f);
            int h4 = (int)floorf(hv * 0.25f);
            int left   = max((cx - (w4 >> 1)) >> 1, 0);   // >>1 == floor-div 2
            int right  = min((cx + (w4 >> 1)) >> 1, HH / 2);
            int top    = max((cy - (h4 >> 1)) >> 1, 0);
            int bottom = min((cy + (h4 >> 1)) >> 1, WW / 2);
            int wr = right - left, hc = bottom - top;
            int M = (wr > 0 && hc > 0) ? wr * hc : 0;
            M = min(M, KARR);    // guaranteed by input ranges; safety clamp
            K = min(CANDK, M);
            if (M > 0) {
                int Mr = (M + TPB - 1) & ~(TPB - 1);   // <= KARR
                // ONE global phase: window values + off/size prefetch together
                for (int t = tid; t < M; t += TPB) {
                    int r = left + t / hc;
                    int c = top + t % hc;
                    int rc = r * WW + c;
                    float vv = clsb[ch * HH * WW + rc];
                    u.b.keys_v[t] = __float_as_uint(vv);
                    u.b.keys_i[t] = (unsigned short)rc;
                    u.b.o0[t] = offp[(b * 2 + 0) * HH * WW + rc];
                    u.b.o1[t] = offp[(b * 2 + 1) * HH * WW + rc];
                    u.b.s0[t] = sizep[(b * 2 + 0) * HH * WW + rc];
                    u.b.s1[t] = sizep[(b * 2 + 1) * HH * WW + rc];
                }
                for (int t = M + tid; t < Mr; t += TPB) u.b.keys_v[t] = 0xFFFFFFFFu;
                __syncthreads();

                unsigned V = 0xFFFFFFFFu;   // M <= K: select all
                unsigned Ti = 0xFFFFu;      // inclusive index threshold at v==V
                if (M > K) {
                    // ---- 4-pass radix-select of Kth smallest VALUE ----
                    if (tid == 0) { s_pfx = 0u; s_kth = K; }
                    __syncthreads();
                    #pragma unroll
                    for (int pi = 0; pi < 4; pi++) {
                        const int d = 24 - 8 * pi;
                        if (tid < 256) hist[tid] = 0;
                        __syncthreads();
                        unsigned pfx = s_pfx;
                        int kth = s_kth;
                        for (int i = tid; i < Mr; i += TPB) {
                            unsigned v = u.b.keys_v[i];
                            if (pi == 0 || (v >> (d + 8)) == pfx)
                                atomicAdd(&hist[(v >> d) & 255], 1);
                        }
                        __syncthreads();
                        if (tid < 256) {
                            int h0 = hist[tid];
                            int h = h0;
                            #pragma unroll
                            for (int o = 1; o < 32; o <<= 1) {
                                int n = __shfl_up_sync(0xffffffffu, h, o);
                                if (lane >= o) h += n;
                            }
                            if (lane == 31) wsum[wrp] = h;
                            __syncwarp();
                        }
                        __syncthreads();
                        if (tid < 8) {
                            int s = wsum[tid];
                            #pragma unroll
                            for (int o = 1; o < 8; o <<= 1) {
                                int n = __shfl_up_sync(0xffu, s, o);
                                if (tid >= o) s += n;
                            }
                            wsum[tid] = s;
                        }
                        __syncthreads();
                        if (tid < 256) {
                            int h0 = hist[tid];
                            int h = h0;
                            #pragma unroll
                            for (int o = 1; o < 32; o <<= 1) {
                                int n = __shfl_up_sync(0xffffffffu, h, o);
                                if (lane >= o) h += n;
                            }
                            int cum = h + (wrp ? wsum[wrp - 1] : 0);
                            if (cum - h0 < kth && kth <= cum) {   // one thread
                                s_kth = kth - (cum - h0);
                                s_pfx = (pfx << 8) | (unsigned)tid;
                                if (pi == 3) s_eq = h0;
                            }
                        }
                        __syncthreads();
                    }
                    V = s_pfx;
                    int needed = s_kth, eqc = s_eq;
                    if (needed < eqc) {
                        // ---- rare: tie-break on index (2x7-bit radix) ----
                        if (tid == 0) s_pfx = 0u;
                        __syncthreads();
                        #pragma unroll
                        for (int pi = 0; pi < 2; pi++) {
                            const int d = 7 - 7 * pi;
                            if (tid < 128) hist[tid] = 0;
                            __syncthreads();
                            unsigned pfx = s_pfx;
                            int kth = s_kth;
                            for (int i = tid; i < Mr; i += TPB) {
                                if (u.b.keys_v[i] == V) {
                                    unsigned ix = u.b.keys_i[i];
                                    if (pi == 0 || (ix >> (d + 7)) == pfx)
                                        atomicAdd(&hist[(ix >> d) & 127], 1);
                                }
                            }
                            __syncthreads();
                            if (tid < 128) {
                                int h0 = hist[tid];
                                int h = h0;
                                #pragma unroll
                                for (int o = 1; o < 32; o <<= 1) {
                                    int n = __shfl_up_sync(0xffffffffu, h, o);
                                    if (lane >= o) h += n;
                                }
                                if (lane == 31) wsum[wrp] = h;
                                __syncwarp();
                            }
                            __syncthreads();
                            if (tid < 4) {
                                int s = wsum[tid];
                                #pragma unroll
                                for (int o = 1; o < 4; o <<= 1) {
                                    int n = __shfl_up_sync(0xfu, s, o);
                                    if (tid >= o) s += n;
                                }
                                wsum[tid] = s;
                            }
                            __syncthreads();
                            if (tid < 128) {
                                int h0 = hist[tid];
                                int h = h0;
                                #pragma unroll
                                for (int o = 1; o < 32; o <<= 1) {
                                    int n = __shfl_up_sync(0xffffffffu, h, o);
                                    if (lane >= o) h += n;
                                }
                                int cum = h + (wrp ? wsum[wrp - 1] : 0);
                                if (cum - h0 < kth && kth <= cum) {
                                    s_kth = kth - (cum - h0);
                                    s_pfx = (s_pfx << 7) | (unsigned)tid;
                                }
                            }
                            __syncthreads();
                        }
                        Ti = s_pfx;   // include idx <= Ti among v==V
                    }
                }

                float cxf = wv * 0.5f * 0.25f;
                float cyf = hv * 0.5f * 0.25f;
                float off0 = cxf - floorf(cxf);
                float off1 = cyf - floorf(cyf);
                // final accumulation: shared-only (no global gather)
                for (int t = tid; t < M; t += TPB) {
                    unsigned v = u.b.keys_v[t];
                    unsigned ix = u.b.keys_i[t];
                    if (v < V || (v == V && ix <= Ti)) {
                        sO += fabsf(u.b.o0[t] - off0) + fabsf(u.b.o1[t] - off1);
                        sS += fabsf(u.b.s0[t] - wv) + fabsf(u.b.s1[t] - hv);
                    }
                }
            }
        }
        #pragma unroll
        for (int o = 16; o; o >>= 1) {
            sO += __shfl_down_sync(0xffffffffu, sO, o);
            sS += __shfl_down_sync(0xffffffffu, sS, o);
        }
        __syncthreads();
        if (lane == 0) { wsf[wrp] = sO; wsd[wrp] = (double)sS; }
        __syncthreads();
        if (tid == 0) {
            float aO = 0.f, aS = 0.f;
            #pragma unroll
            for (int k = 0; k < 16; k++) { aO += wsf[k]; aS += (float)wsd[k]; }
            g_off[b] = aO;
            g_size[b] = aS;
            g_npos[b] = K;
        }
    }

    // ================= last-block combine =================
    __threadfence();
    __syncthreads();
    if (tid == 0) s_flag = (atomicAdd(&g_done, 1) == NBLK - 1);
    __syncthreads();
    if (s_flag) {
        __threadfence();
        double acc = 0.0;
        for (int i2 = tid; i2 < FBLK; i2 += TPB) acc += g_focal[i2];
        #pragma unroll
        for (int o = 16; o; o >>= 1) acc += __shfl_down_sync(0xffffffffu, acc, o);
        if (lane == 0) wsd[wrp] = acc;
        __syncthreads();
        if (tid == 0) {
            double fsum = 0.0;
            #pragma unroll
            for (int k = 0; k < 16; k++) fsum += wsd[k];
            double corr = 0.0, offs = 0.0, szs = 0.0;
            int npos = 0;
            for (int b2 = 0; b2 < BB; b2++) {
                corr += (double)g_corr[b2];
                offs += (double)g_off[b2];
                szs  += (double)g_size[b2];
                npos += g_npos[b2];
            }
            double np = (double)max(npos, 1);
            double cls_loss = -(fsum + corr) / (double)(BB * HH * WW);
            out[0] = (float)(cls_loss + 0.1 * (szs / np) + (offs / np));
            g_done = 0;   // reset for next graph replay
        }
    }
}

extern "C" void kernel_launch(void* const* d_in, const int* in_sizes, int n_in,
                              void* d_out, int out_size) {
    const float* cls_pred    = (const float*)d_in[0];
    const float* offset_pred = (const float*)d_in[1];
    const float* size_pred   = (const float*)d_in[2];
    const float* gt_box      = (const float*)d_in[3];
    const int*   gt_class    = (const int*)d_in[4];
    float* out = (float*)d_out;
    (void)in_sizes; (void)n_in; (void)out_size;

    fused_kernel<<<NBLK, TPB>>>((const float4*)cls_pred, cls_pred,
                                offset_pred, size_pred, gt_box, gt_class, out);
}